// round 13
// baseline (speedup 1.0000x reference)
#include <cuda_runtime.h>
#include <math.h>
#include <stdint.h>

typedef unsigned long long ull;

#define NB 128
#define ND 256
#define NH 1024
#define NT 512
#define NH3 3072
#define NBLK 128
#define NTHR 256

// ---------------- scratch (static device globals) ---------------------------
__device__ float    g_P[(size_t)NT * NB * NH3];   // x-projections (+bias)
__device__ float    g_gamma[NT * NH];
__device__ uint32_t g_atf[NB * NH];               // a = gamma*h, tf32 bits
__device__ uint32_t g_ratf[NB * NH];              // r*a, tf32 bits
__device__ float    g_zrpart[8][NB * 2 * NH];
__device__ float    g_hpart[8][NB * NH];

// ---------------- grid barriers ----------------------------------------------
__device__ unsigned g_bar_count = 0;
__device__ volatile unsigned g_bar_gen = 0;
__device__ unsigned g_flagsP[NBLK];               // packed: 512 B = 4 cache lines

__device__ __forceinline__ void gridbar_atomic() {
    __syncthreads();
    if (threadIdx.x == 0) {
        unsigned gen = g_bar_gen;
        __threadfence();
        if (atomicAdd(&g_bar_count, 1) == NBLK - 1) {
            g_bar_count = 0;
            __threadfence();
            g_bar_gen = gen + 1;
        } else {
            while (g_bar_gen == gen) {}
            __threadfence();
        }
    }
    __syncthreads();
}

__device__ __forceinline__ void gridbar(unsigned gen) {
    __syncthreads();
    if (threadIdx.x == 0) {
        __threadfence();
        *(volatile unsigned*)&g_flagsP[blockIdx.x] = gen;
    }
    if (threadIdx.x < NBLK) {
        while (*(volatile unsigned*)&g_flagsP[threadIdx.x] < gen) {}
    }
    __threadfence();
    __syncthreads();
}

// ---------------- helpers ----------------------------------------------------
__device__ __forceinline__ float sigmf(float x) { return 1.f / (1.f + expf(-x)); }

__device__ __forceinline__ uint32_t cvt_tf32(float x) {
    uint32_t r; asm("cvt.rna.tf32.f32 %0, %1;" : "=r"(r) : "f"(x)); return r;
}
__device__ __forceinline__ uint32_t smem_u32(const void* p) {
    uint32_t a;
    asm("{ .reg .u64 t; cvta.to.shared.u64 t, %1; cvt.u32.u64 %0, t; }" : "=r"(a) : "l"(p));
    return a;
}

#define MMA_TF32(d, a, b0, b1) \
    asm volatile("mma.sync.aligned.m16n8k8.row.col.f32.tf32.tf32.f32 " \
        "{%0,%1,%2,%3}, {%4,%5,%6,%7}, {%8,%9}, {%0,%1,%2,%3};" \
        : "+f"((d)[0]), "+f"((d)[1]), "+f"((d)[2]), "+f"((d)[3]) \
        : "r"((a)[0]), "r"((a)[1]), "r"((a)[2]), "r"((a)[3]), "r"(b0), "r"(b1))

#define CP_ASYNC16(dst_u32, src_ptr) \
    asm volatile("cp.async.cg.shared.global [%0], [%1], 16;" :: "r"(dst_u32), "l"(src_ptr) : "memory")
#define CP_COMMIT() asm volatile("cp.async.commit_group;" ::: "memory")
#define CP_WAIT(n)  asm volatile("cp.async.wait_group %0;" :: "n"(n) : "memory")

#define PAIR_BAR(id) asm volatile("bar.sync %0, 64;" :: "r"(id) : "memory")

#define STG_CS4(p, v) \
    asm volatile("st.global.cs.v4.f32 [%0], {%1,%2,%3,%4};" \
        :: "l"(p), "f"((v).x), "f"((v).y), "f"((v).z), "f"((v).w) : "memory")

// persist smem layout (bytes)
#define STRA      132                     // A row stride in 4B words
#define OFF_AS    0                       // 128*132*4 = 67584
#define OFF_BAF   67584                   // 16*16*32*8 = 65536
#define OFF_BCF   133120                  // 16*8*32*8  = 32768
#define OFF_AROW  165888                  // 4096 (a row, float)
#define OFF_ZROW  169984                  // 4096 (z row, float)
#define SMEM_DYN  174080

// per-warp fill: warp covers its m-strip [mbase, mbase+32), k-quarter
// [wn*64 + s*32, +32). 8 float4 per lane per stage.
#define FILL_WARP_STAGE(src, s) \
    do { \
        _Pragma("unroll") \
        for (int i = 0; i < 8; i++) { \
            int e = i * 32 + lid; \
            int row = e >> 3, kq = e & 7; \
            int m = mbase + row; \
            int k = wn * 64 + (s) * 32 + kq * 4; \
            uint32_t d = sb + OFF_AS + (uint32_t)(m * STRA + k) * 4; \
            CP_ASYNC16(d, (const void*)((src) + (size_t)m * NH + kbase + k)); \
        } \
        CP_COMMIT(); \
    } while (0)

// ---------------- x-projection GEMM (tf32 MMA, 2 CTAs/SM) --------------------
__global__ __launch_bounds__(256, 2) void k_xproj(
    const float* __restrict__ value,
    const float* __restrict__ wxz, const float* __restrict__ wxr,
    const float* __restrict__ wxh,
    const float* __restrict__ bbz, const float* __restrict__ bbr,
    const float* __restrict__ bbh)
{
    __shared__ uint32_t As[32 * 132];     // [k][m], stride 132
    __shared__ uint32_t Bs[128 * 36];     // [n][k], stride 36
    const int n0 = blockIdx.x * 128;
    const int m0 = blockIdx.y * 128;
    const int gate = n0 >> 10;
    const int j0 = n0 & (NH - 1);
    const float* W    = (gate == 0) ? wxz : (gate == 1 ? wxr : wxh);
    const float* bias = (gate == 0) ? bbz : (gate == 1 ? bbr : bbh);
    const int b  = m0 >> 9;
    const int t0 = m0 & (NT - 1);
    const int tid = threadIdx.x;
    const int wid = tid >> 5, lid = tid & 31;
    const int gid = lid >> 2, tig = lid & 3;
    const int mbase = (wid & 3) * 32;
    const int nstrip = (wid >> 2) * 64;

    float acc[2][8][4];
#pragma unroll
    for (int mt = 0; mt < 2; mt++)
#pragma unroll
        for (int nt = 0; nt < 8; nt++)
#pragma unroll
            for (int c = 0; c < 4; c++) acc[mt][nt][c] = 0.f;

    const float* Abase = value + (size_t)b * ND * NT + t0;

    for (int kc = 0; kc < ND; kc += 32) {
#pragma unroll
        for (int it = 0; it < 16; it++) {
            int idx = it * 256 + tid;
            int m = idx & 127, k = idx >> 7;
            As[k * 132 + m] = cvt_tf32(Abase[(size_t)(kc + k) * NT + m]);
        }
#pragma unroll
        for (int it = 0; it < 16; it++) {
            int idx = it * 256 + tid;
            int n = idx & 127, k = idx >> 7;
            Bs[n * 36 + k] = cvt_tf32(W[(size_t)(kc + k) * NH + j0 + n]);
        }
        __syncthreads();
#pragma unroll
        for (int kk = 0; kk < 4; kk++) {
            int k0 = kk * 8;
            uint32_t a[2][4];
#pragma unroll
            for (int mt = 0; mt < 2; mt++) {
                int m = mbase + mt * 16 + gid;
                a[mt][0] = As[(k0 + tig) * 132 + m];
                a[mt][1] = As[(k0 + tig) * 132 + m + 8];
                a[mt][2] = As[(k0 + tig + 4) * 132 + m];
                a[mt][3] = As[(k0 + tig + 4) * 132 + m + 8];
            }
#pragma unroll
            for (int nt = 0; nt < 8; nt++) {
                int n = nstrip + nt * 8 + gid;
                uint32_t b0 = Bs[n * 36 + k0 + tig];
                uint32_t b1 = Bs[n * 36 + k0 + tig + 4];
                MMA_TF32(acc[0][nt], a[0], b0, b1);
                MMA_TF32(acc[1][nt], a[1], b0, b1);
            }
        }
        __syncthreads();
    }
#pragma unroll
    for (int mt = 0; mt < 2; mt++) {
        int m = m0 + mbase + mt * 16 + gid;
#pragma unroll
        for (int nt = 0; nt < 8; nt++) {
            int nl = nstrip + nt * 8 + tig * 2;
            float b0v = bias[j0 + nl], b1v = bias[j0 + nl + 1];
            float* dst = g_P + (size_t)m * NH3 + n0 + nl;
            *(float2*)dst = make_float2(acc[mt][nt][0] + b0v, acc[mt][nt][1] + b1v);
            float* dst2 = g_P + (size_t)(m + 8) * NH3 + n0 + nl;
            *(float2*)dst2 = make_float2(acc[mt][nt][2] + b0v, acc[mt][nt][3] + b1v);
        }
    }
}

// ---------------- persistent recurrence kernel (warp-decoupled fills) --------
__global__ __launch_bounds__(NTHR, 1) void k_persist(
    const float* __restrict__ delta,
    const float* __restrict__ wdg, const float* __restrict__ bdg,
    const float* __restrict__ whz, const float* __restrict__ whr,
    const float* __restrict__ whh,
    float* __restrict__ out, float* __restrict__ hlast)
{
    extern __shared__ char smem[];
    const uint32_t sb = smem_u32(smem);
    uint32_t* As  = (uint32_t*)(smem + OFF_AS);   // [m128][k128] stride 132
    ull* BAf      = (ull*)(smem + OFF_BAF);       // frag order [kk16][ntile16][lid32]
    ull* BCf      = (ull*)(smem + OFF_BCF);       // frag order [kk16][ntile8][lid32]
    float4* arow  = (float4*)(smem + OFF_AROW);   // a row (this block's batch row)
    float4* zrow  = (float4*)(smem + OFF_ZROW);   // z row

    const int bid = blockIdx.x;
    const int tid = threadIdx.x;
    const int wid = tid >> 5;
    const int lid = tid & 31;
    const int gid = lid >> 2, tig = lid & 3;
    const int mbase = (wid & 3) * 32;
    const int wn    = wid >> 2;             // 0..1
    const int pbar  = 1 + (wid & 3);        // named pair-barrier id (warps w, w+4)

    // block roles
    const int n0A    = (bid >> 3) * 128;    // zr: N base (0..2047)
    const int ksA    = bid & 7;
    const int kbase  = ksA * 128;           // shared k-slice for A and C
    const int gate   = n0A >> 10;
    const int j0     = n0A & (NH - 1);
    const int n0C    = (bid >> 3) * 64;     // h~: N base (0..1023)
    const int ksC    = bid & 7;

    // ---- prologue: flag reset, gamma, zero state ----
    if (tid == 0) *(volatile unsigned*)&g_flagsP[bid] = 0;

    for (int it = 0; it < 4; it++) {
        int idx4 = bid * 1024 + it * 256 + tid;
        int i = idx4 * 4;
        int t = i >> 10, j = i & (NH - 1);
        float d = delta[t];
        float4 w = *(const float4*)(wdg + j);
        float4 bb = *(const float4*)(bdg + j);
        float4 g;
        g.x = expf(-fmaxf(0.f, w.x * d + bb.x));
        g.y = expf(-fmaxf(0.f, w.y * d + bb.y));
        g.z = expf(-fmaxf(0.f, w.z * d + bb.z));
        g.w = expf(-fmaxf(0.f, w.w * d + bb.w));
        *(float4*)(g_gamma + i) = g;
    }
    float4 a_reg = make_float4(0.f, 0.f, 0.f, 0.f);
    arow[tid] = a_reg;
    *(uint4*)(g_atf + bid * NH + tid * 4) = make_uint4(0u, 0u, 0u, 0u);

    // ---- prologue: stationary weights -> fragment-order smem (tf32) ----
    {
        const float* Wzr = gate ? whr : whz;
#pragma unroll 1
        for (int it = 0; it < 64; it++) {          // 128n x 128k
            int idx = it * 256 + tid;
            int n = idx & 127, k = idx >> 7;
            uint32_t bits = cvt_tf32(Wzr[(size_t)(kbase + k) * NH + j0 + n]);
            int kk = k >> 3, pos = k & 7, ntile = n >> 3, g = n & 7;
            int lane = g * 4 + (pos & 3), half = pos >> 2;
            *(uint32_t*)((char*)BAf + ((size_t)(kk * 16 + ntile) * 32 + lane) * 8 + half * 4) = bits;
        }
#pragma unroll 1
        for (int it = 0; it < 32; it++) {          // 64n x 128k
            int idx = it * 256 + tid;
            int n = idx & 63, k = idx >> 6;
            uint32_t bits = cvt_tf32(whh[(size_t)(kbase + k) * NH + n0C + n]);
            int kk = k >> 3, pos = k & 7, ntile = n >> 3, g = n & 7;
            int lane = g * 4 + (pos & 3), half = pos >> 2;
            *(uint32_t*)((char*)BCf + ((size_t)(kk * 8 + ntile) * 32 + lane) * 8 + half * 4) = bits;
        }
    }
    gridbar_atomic();      // publishes flag reset + gamma + atf + weights
    unsigned gen = 0;

    // kk visit order: first pair-stage covers kk {0-3, 8-11}, second the rest
    const int kkset0[8] = {0, 1, 2, 3, 8, 9, 10, 11};
    const int kkset1[8] = {4, 5, 6, 7, 12, 13, 14, 15};

    for (int t = 0; t < NT; t++) {
        // ---- prefetch P rows (B, D) and gamma(t+1) ----
        const float4* Pp = (const float4*)(g_P + ((size_t)(bid * NT + t)) * NH3);
        float4 pz  = __ldg(Pp + tid);
        float4 pr  = __ldg(Pp + 256 + tid);
        float4 phh = __ldg(Pp + 512 + tid);
        int tn = (t + 1 < NT) ? t + 1 : t;
        float4 gn = __ldg((const float4*)(g_gamma + tn * NH) + tid);

        // ---- Phase A: zr partial = a @ [Whz|Whr]  (M128,N128,K128) ----
        {
            FILL_WARP_STAGE(g_atf, 0);
            FILL_WARP_STAGE(g_atf, 1);

            float acc[2][8][4];
#pragma unroll
            for (int mt = 0; mt < 2; mt++)
#pragma unroll
                for (int nt = 0; nt < 8; nt++)
#pragma unroll
                    for (int c = 0; c < 4; c++) acc[mt][nt][c] = 0.f;

#pragma unroll
            for (int stg = 0; stg < 2; stg++) {
                if (stg == 0) CP_WAIT(1); else CP_WAIT(0);
                PAIR_BAR(pbar);
                const int* kks = stg == 0 ? kkset0 : kkset1;
#pragma unroll
                for (int q = 0; q < 8; q++) {
                    int kk = kks[q];
                    int k0 = kk * 8;
                    uint32_t a[2][4];
#pragma unroll
                    for (int mt = 0; mt < 2; mt++) {
                        const uint32_t* ap = As + (mbase + mt * 16 + gid) * STRA + k0 + tig;
                        a[mt][0] = ap[0];
                        a[mt][1] = ap[8 * STRA];
                        a[mt][2] = ap[4];
                        a[mt][3] = ap[8 * STRA + 4];
                    }
                    const ull* bp = BAf + (size_t)(kk * 16 + wn * 8) * 32 + lid;
#pragma unroll
                    for (int nt = 0; nt < 8; nt++) {
                        ull bb = bp[nt * 32];
                        uint32_t b0 = (uint32_t)bb, b1 = (uint32_t)(bb >> 32);
                        MMA_TF32(acc[0][nt], a[0], b0, b1);
                        MMA_TF32(acc[1][nt], a[1], b0, b1);
                    }
                }
            }
            float* dst = g_zrpart[ksA];
#pragma unroll
            for (int mt = 0; mt < 2; mt++) {
                int m = mbase + mt * 16 + gid;
#pragma unroll
                for (int nt = 0; nt < 8; nt++) {
                    int n = n0A + wn * 64 + nt * 8 + tig * 2;
                    *(float2*)&dst[m * (2 * NH) + n] =
                        make_float2(acc[mt][nt][0], acc[mt][nt][1]);
                    *(float2*)&dst[(m + 8) * (2 * NH) + n] =
                        make_float2(acc[mt][nt][2], acc[mt][nt][3]);
                }
            }
        }
        gridbar(++gen);

        // ---- Phase B: z, r gates; z -> smem, ra(tf32) -> global ----
        {
            float4 sz = pz, sr = pr;
#pragma unroll
            for (int ks = 0; ks < 8; ks++) {
                const float4* zp = (const float4*)(g_zrpart[ks] + bid * 2 * NH);
                float4 v = zp[tid];
                sz.x += v.x; sz.y += v.y; sz.z += v.z; sz.w += v.w;
                float4 w = zp[256 + tid];
                sr.x += w.x; sr.y += w.y; sr.z += w.z; sr.w += w.w;
            }
            float4 zf = make_float4(sigmf(sz.x), sigmf(sz.y), sigmf(sz.z), sigmf(sz.w));
            float4 rf = make_float4(sigmf(sr.x), sigmf(sr.y), sigmf(sr.z), sigmf(sr.w));
            zrow[tid] = zf;
            float4 av = arow[tid];
            uint4 u;
            u.x = cvt_tf32(rf.x * av.x);
            u.y = cvt_tf32(rf.y * av.y);
            u.z = cvt_tf32(rf.z * av.z);
            u.w = cvt_tf32(rf.w * av.w);
            *(uint4*)(g_ratf + bid * NH + tid * 4) = u;
        }
        gridbar(++gen);

        // ---- Phase C: h~ partial = (r*a) @ Whh  (M128,N64,K128) ----
        {
            FILL_WARP_STAGE(g_ratf, 0);
            FILL_WARP_STAGE(g_ratf, 1);

            float acc[2][4][4];
#pragma unroll
            for (int mt = 0; mt < 2; mt++)
#pragma unroll
                for (int nt = 0; nt < 4; nt++)
#pragma unroll
                    for (int c = 0; c < 4; c++) acc[mt][nt][c] = 0.f;

#pragma unroll
            for (int stg = 0; stg < 2; stg++) {
                if (stg == 0) CP_WAIT(1); else CP_WAIT(0);
                PAIR_BAR(pbar);
                const int* kks = stg == 0 ? kkset0 : kkset1;
#pragma unroll
                for (int q = 0; q < 8; q++) {
                    int kk = kks[q];
                    int k0 = kk * 8;
                    uint32_t a[2][4];
#pragma unroll
                    for (int mt = 0; mt < 2; mt++) {
                        const uint32_t* ap = As + (mbase + mt * 16 + gid) * STRA + k0 + tig;
                        a[mt][0] = ap[0];
                        a[mt][1] = ap[8 * STRA];
                        a[mt][2] = ap[4];
                        a[mt][3] = ap[8 * STRA + 4];
                    }
                    const ull* bp = BCf + (size_t)(kk * 8 + wn * 4) * 32 + lid;
#pragma unroll
                    for (int nt = 0; nt < 4; nt++) {
                        ull bb = bp[nt * 32];
                        uint32_t b0 = (uint32_t)bb, b1 = (uint32_t)(bb >> 32);
                        MMA_TF32(acc[0][nt], a[0], b0, b1);
                        MMA_TF32(acc[1][nt], a[1], b0, b1);
                    }
                }
            }
            float* dst = g_hpart[ksC];
#pragma unroll
            for (int mt = 0; mt < 2; mt++) {
                int m = mbase + mt * 16 + gid;
#pragma unroll
                for (int nt = 0; nt < 4; nt++) {
                    int n = n0C + wn * 32 + nt * 8 + tig * 2;
                    *(float2*)&dst[m * NH + n] =
                        make_float2(acc[mt][nt][0], acc[mt][nt][1]);
                    *(float2*)&dst[(m + 8) * NH + n] =
                        make_float2(acc[mt][nt][2], acc[mt][nt][3]);
                }
            }
        }
        gridbar(++gen);

        // ---- Phase D: h update, output (streaming), next a ----
        {
            float4 sh = phh;
#pragma unroll
            for (int ks = 0; ks < 8; ks++) {
                const float4* hp = (const float4*)(g_hpart[ks] + bid * NH);
                float4 v = hp[tid];
                sh.x += v.x; sh.y += v.y; sh.z += v.z; sh.w += v.w;
            }
            float4 zz = zrow[tid];
            float4 aa = a_reg;
            float4 hn;
            hn.x = (1.f - zz.x) * aa.x + zz.x * tanhf(sh.x);
            hn.y = (1.f - zz.y) * aa.y + zz.y * tanhf(sh.y);
            hn.z = (1.f - zz.z) * aa.z + zz.z * tanhf(sh.z);
            hn.w = (1.f - zz.w) * aa.w + zz.w * tanhf(sh.w);
            STG_CS4(out + ((size_t)(bid * NT + t)) * NH + tid * 4, hn);
            if (t + 1 < NT) {
                float4 an = make_float4(gn.x * hn.x, gn.y * hn.y, gn.z * hn.z, gn.w * hn.w);
                a_reg = an;
                arow[tid] = an;
                uint4 u;
                u.x = cvt_tf32(an.x); u.y = cvt_tf32(an.y);
                u.z = cvt_tf32(an.z); u.w = cvt_tf32(an.w);
                *(uint4*)(g_atf + bid * NH + tid * 4) = u;
            } else {
                *(float4*)(hlast + bid * NH + tid * 4) = hn;
            }
        }
        gridbar(++gen);
    }
}

// ---------------- launch -----------------------------------------------------
extern "C" void kernel_launch(void* const* d_in, const int* in_sizes, int n_in,
                              void* d_out, int out_size) {
    const float* value = (const float*)d_in[0];
    const float* delta = (const float*)d_in[1];
    const float* wdg   = (const float*)d_in[2];
    const float* wxz   = (const float*)d_in[3];
    const float* whz   = (const float*)d_in[4];
    const float* wxr   = (const float*)d_in[5];
    const float* whr   = (const float*)d_in[6];
    const float* wxh   = (const float*)d_in[7];
    const float* whh   = (const float*)d_in[8];
    const float* bdg   = (const float*)d_in[9];
    const float* bz    = (const float*)d_in[10];
    const float* br    = (const float*)d_in[11];
    const float* bh    = (const float*)d_in[12];
    float* out = (float*)d_out;
    float* hlast = out + ((size_t)out_size - (size_t)NB * NH);

    cudaFuncSetAttribute(k_persist, cudaFuncAttributeMaxDynamicSharedMemorySize, SMEM_DYN);

    k_xproj<<<dim3(24, 512), 256>>>(value, wxz, wxr, wxh, bz, br, bh);
    k_persist<<<NBLK, NTHR, SMEM_DYN>>>(delta, wdg, bdg, whz, whr, whh, out, hlast);
}

// round 14
// speedup vs baseline: 1.4292x; 1.4292x over previous
#include <cuda_runtime.h>
#include <math.h>
#include <stdint.h>

typedef unsigned long long ull;

#define NB 128
#define ND 256
#define NH 1024
#define NT 512
#define NH3 3072
#define NBLK 128
#define NTHR 256

// ---------------- scratch (static device globals) ---------------------------
__device__ float    g_P[(size_t)NT * NB * NH3];   // x-projections (+bias)
__device__ float    g_gamma[NT * NH];
__device__ uint32_t g_atf[NB * NH];               // a = gamma*h, tf32 bits
__device__ uint32_t g_ratf[NB * NH];              // r*a, tf32 bits
__device__ float    g_z[NB * NH];                 // z gates (row-major)
__device__ float    g_zrpartT[8][2048 * 128];     // zr partials TRANSPOSED [ks][n][b]
__device__ float    g_hpart[8][NB * NH];

// ---------------- sync objects ------------------------------------------------
__device__ unsigned g_bar_count = 0;
__device__ volatile unsigned g_bar_gen = 0;
__device__ unsigned g_flags[NBLK * 32];           // per-block 128B line (global bar)
__device__ unsigned g_zrcnt[16 * 32];             // per zr-n-tile producer counter
__device__ unsigned g_rdone[16 * 32];             // per zr-n-tile reducer counter

__device__ __forceinline__ void gridbar_atomic() {
    __syncthreads();
    if (threadIdx.x == 0) {
        unsigned gen = g_bar_gen;
        __threadfence();
        if (atomicAdd(&g_bar_count, 1) == NBLK - 1) {
            g_bar_count = 0;
            __threadfence();
            g_bar_gen = gen + 1;
        } else {
            while (g_bar_gen == gen) {}
            __threadfence();
        }
    }
    __syncthreads();
}

__device__ __forceinline__ void gridbar(unsigned gen) {
    __syncthreads();
    if (threadIdx.x == 0) {
        __threadfence();
        *(volatile unsigned*)&g_flags[blockIdx.x * 32] = gen;
    }
    if (threadIdx.x < NBLK) {
        while (*(volatile unsigned*)&g_flags[threadIdx.x * 32] < gen) {}
    }
    __threadfence();
    __syncthreads();
}

#define RED_ADD1(p) \
    asm volatile("red.global.add.u32 [%0], %1;" :: "l"(p), "r"(1u) : "memory")

// block-wide release-arrive on a counter
__device__ __forceinline__ void cnt_arrive(unsigned* cnt) {
    __syncthreads();
    if (threadIdx.x == 0) { __threadfence(); RED_ADD1(cnt); }
}
// block-wide acquire-wait on a counter
__device__ __forceinline__ void cnt_wait(unsigned* cnt, unsigned target) {
    if (threadIdx.x == 0) {
        while (*(volatile unsigned*)cnt < target) {}
        __threadfence();
    }
    __syncthreads();
}

// ---------------- helpers ----------------------------------------------------
__device__ __forceinline__ float sigmf(float x) { return 1.f / (1.f + expf(-x)); }

__device__ __forceinline__ uint32_t cvt_tf32(float x) {
    uint32_t r; asm("cvt.rna.tf32.f32 %0, %1;" : "=r"(r) : "f"(x)); return r;
}
__device__ __forceinline__ uint32_t smem_u32(const void* p) {
    uint32_t a;
    asm("{ .reg .u64 t; cvta.to.shared.u64 t, %1; cvt.u32.u64 %0, t; }" : "=r"(a) : "l"(p));
    return a;
}

#define MMA_TF32(d, a, b0, b1) \
    asm volatile("mma.sync.aligned.m16n8k8.row.col.f32.tf32.tf32.f32 " \
        "{%0,%1,%2,%3}, {%4,%5,%6,%7}, {%8,%9}, {%0,%1,%2,%3};" \
        : "+f"((d)[0]), "+f"((d)[1]), "+f"((d)[2]), "+f"((d)[3]) \
        : "r"((a)[0]), "r"((a)[1]), "r"((a)[2]), "r"((a)[3]), "r"(b0), "r"(b1))

#define CP_ASYNC16(dst_u32, src_ptr) \
    asm volatile("cp.async.cg.shared.global [%0], [%1], 16;" :: "r"(dst_u32), "l"(src_ptr) : "memory")
#define CP_COMMIT() asm volatile("cp.async.commit_group;" ::: "memory")
#define CP_WAIT(n)  asm volatile("cp.async.wait_group %0;" :: "n"(n) : "memory")

#define PAIR_BAR(id) asm volatile("bar.sync %0, 64;" :: "r"(id) : "memory")

#define STG_CS4(p, v) \
    asm volatile("st.global.cs.v4.f32 [%0], {%1,%2,%3,%4};" \
        :: "l"(p), "f"((v).x), "f"((v).y), "f"((v).z), "f"((v).w) : "memory")

// persist smem layout (bytes)
#define STRA      132                     // A row stride in 4B words
#define OFF_AS    0                       // 128*132*4 = 67584
#define OFF_BAF   67584                   // 16*16*32*8 = 65536
#define OFF_BCF   133120                  // 16*8*32*8  = 32768
#define SMEM_DYN  165888

// per-warp fill: warp covers m-strip [mbase, mbase+32), k-quarter
#define FILL_WARP_STAGE(src, s) \
    do { \
        _Pragma("unroll") \
        for (int i = 0; i < 8; i++) { \
            int e = i * 32 + lid; \
            int row = e >> 3, kq = e & 7; \
            int m = mbase + row; \
            int k = wn * 64 + (s) * 32 + kq * 4; \
            uint32_t d = sb + OFF_AS + (uint32_t)(m * STRA + k) * 4; \
            CP_ASYNC16(d, (const void*)((src) + (size_t)m * NH + kbase + k)); \
        } \
        CP_COMMIT(); \
    } while (0)

// ---------------- x-projection GEMM (tf32 MMA) --------------------------------
__global__ __launch_bounds__(256) void k_xproj(
    const float* __restrict__ value,
    const float* __restrict__ wxz, const float* __restrict__ wxr,
    const float* __restrict__ wxh,
    const float* __restrict__ bbz, const float* __restrict__ bbr,
    const float* __restrict__ bbh)
{
    __shared__ uint32_t As[32 * 132];
    __shared__ uint32_t Bs[128 * 36];
    const int n0 = blockIdx.x * 128;
    const int m0 = blockIdx.y * 128;
    const int gate = n0 >> 10;
    const int j0 = n0 & (NH - 1);
    const float* W    = (gate == 0) ? wxz : (gate == 1 ? wxr : wxh);
    const float* bias = (gate == 0) ? bbz : (gate == 1 ? bbr : bbh);
    const int b  = m0 >> 9;
    const int t0 = m0 & (NT - 1);
    const int tid = threadIdx.x;
    const int wid = tid >> 5, lid = tid & 31;
    const int gid = lid >> 2, tig = lid & 3;
    const int mbase = (wid & 3) * 32;
    const int nstrip = (wid >> 2) * 64;

    float acc[2][8][4];
#pragma unroll
    for (int mt = 0; mt < 2; mt++)
#pragma unroll
        for (int nt = 0; nt < 8; nt++)
#pragma unroll
            for (int c = 0; c < 4; c++) acc[mt][nt][c] = 0.f;

    const float* Abase = value + (size_t)b * ND * NT + t0;

    for (int kc = 0; kc < ND; kc += 32) {
#pragma unroll
        for (int it = 0; it < 16; it++) {
            int idx = it * 256 + tid;
            int m = idx & 127, k = idx >> 7;
            As[k * 132 + m] = cvt_tf32(Abase[(size_t)(kc + k) * NT + m]);
        }
#pragma unroll
        for (int it = 0; it < 16; it++) {
            int idx = it * 256 + tid;
            int n = idx & 127, k = idx >> 7;
            Bs[n * 36 + k] = cvt_tf32(W[(size_t)(kc + k) * NH + j0 + n]);
        }
        __syncthreads();
#pragma unroll
        for (int kk = 0; kk < 4; kk++) {
            int k0 = kk * 8;
            uint32_t a[2][4];
#pragma unroll
            for (int mt = 0; mt < 2; mt++) {
                int m = mbase + mt * 16 + gid;
                a[mt][0] = As[(k0 + tig) * 132 + m];
                a[mt][1] = As[(k0 + tig) * 132 + m + 8];
                a[mt][2] = As[(k0 + tig + 4) * 132 + m];
                a[mt][3] = As[(k0 + tig + 4) * 132 + m + 8];
            }
#pragma unroll
            for (int nt = 0; nt < 8; nt++) {
                int n = nstrip + nt * 8 + gid;
                uint32_t b0 = Bs[n * 36 + k0 + tig];
                uint32_t b1 = Bs[n * 36 + k0 + tig + 4];
                MMA_TF32(acc[0][nt], a[0], b0, b1);
                MMA_TF32(acc[1][nt], a[1], b0, b1);
            }
        }
        __syncthreads();
    }
#pragma unroll
    for (int mt = 0; mt < 2; mt++) {
        int m = m0 + mbase + mt * 16 + gid;
#pragma unroll
        for (int nt = 0; nt < 8; nt++) {
            int nl = nstrip + nt * 8 + tig * 2;
            float b0v = bias[j0 + nl], b1v = bias[j0 + nl + 1];
            float* dst = g_P + (size_t)m * NH3 + n0 + nl;
            *(float2*)dst = make_float2(acc[mt][nt][0] + b0v, acc[mt][nt][1] + b1v);
            float* dst2 = g_P + (size_t)(m + 8) * NH3 + n0 + nl;
            *(float2*)dst2 = make_float2(acc[mt][nt][2] + b0v, acc[mt][nt][3] + b1v);
        }
    }
}

// ---------------- persistent recurrence (local flags + 2 global bars) --------
__global__ __launch_bounds__(NTHR, 1) void k_persist(
    const float* __restrict__ delta,
    const float* __restrict__ wdg, const float* __restrict__ bdg,
    const float* __restrict__ whz, const float* __restrict__ whr,
    const float* __restrict__ whh,
    float* __restrict__ out, float* __restrict__ hlast)
{
    extern __shared__ char smem[];
    const uint32_t sb = smem_u32(smem);
    uint32_t* As  = (uint32_t*)(smem + OFF_AS);   // [m128][k128] stride 132
    ull* BAf      = (ull*)(smem + OFF_BAF);       // frag order [kk16][ntile16][lid32]
    ull* BCf      = (ull*)(smem + OFF_BCF);       // frag order [kk16][ntile8][lid32]

    const int bid = blockIdx.x;
    const int tid = threadIdx.x;
    const int wid = tid >> 5;
    const int lid = tid & 31;
    const int gid = lid >> 2, tig = lid & 3;
    const int mbase = (wid & 3) * 32;
    const int wn    = wid >> 2;             // 0..1
    const int pbar  = 1 + (wid & 3);        // named pair-barrier id

    // block roles
    const int ntA    = bid >> 3;            // zr n-tile 0..15 (A producer + B reducer tile)
    const int ksA    = bid & 7;
    const int n0A    = ntA * 128;
    const int kbase  = ksA * 128;           // shared k-slice for A and C
    const int gate   = n0A >> 10;
    const int j0     = n0A & (NH - 1);
    const int n0C    = (bid >> 3) * 64;     // h~: N base (0..1023)
    const int ksC    = bid & 7;
    const int bsB    = bid & 7;             // B role: b-slice
    const int ntB    = ntA;                 // B role: same n-tile index
    const int bb     = bsB * 16 + (tid & 15);   // B role: batch row
    const int c0B    = tid >> 4;                // B role: col base 0..15

    // ---- prologue: flag/counter reset, gamma, zero state ----
    if (tid == 0) {
        *(volatile unsigned*)&g_flags[bid * 32] = 0;
        if (bid < 16) {
            *(volatile unsigned*)&g_zrcnt[bid * 32] = 0;
            *(volatile unsigned*)&g_rdone[bid * 32] = 0;
        }
    }

    for (int it = 0; it < 4; it++) {
        int idx4 = bid * 1024 + it * 256 + tid;
        int i = idx4 * 4;
        int t = i >> 10, j = i & (NH - 1);
        float d = delta[t];
        float4 w = *(const float4*)(wdg + j);
        float4 bbv = *(const float4*)(bdg + j);
        float4 g;
        g.x = expf(-fmaxf(0.f, w.x * d + bbv.x));
        g.y = expf(-fmaxf(0.f, w.y * d + bbv.y));
        g.z = expf(-fmaxf(0.f, w.z * d + bbv.z));
        g.w = expf(-fmaxf(0.f, w.w * d + bbv.w));
        *(float4*)(g_gamma + i) = g;
    }
    float4 a_reg = make_float4(0.f, 0.f, 0.f, 0.f);
    *(uint4*)(g_atf + bid * NH + tid * 4) = make_uint4(0u, 0u, 0u, 0u);

    // ---- prologue: stationary weights -> fragment-order smem (tf32) ----
    {
        const float* Wzr = gate ? whr : whz;
#pragma unroll 1
        for (int it = 0; it < 64; it++) {          // 128n x 128k
            int idx = it * 256 + tid;
            int n = idx & 127, k = idx >> 7;
            uint32_t bits = cvt_tf32(Wzr[(size_t)(kbase + k) * NH + j0 + n]);
            int kk = k >> 3, pos = k & 7, ntile = n >> 3, g = n & 7;
            int lane = g * 4 + (pos & 3), half = pos >> 2;
            *(uint32_t*)((char*)BAf + ((size_t)(kk * 16 + ntile) * 32 + lane) * 8 + half * 4) = bits;
        }
#pragma unroll 1
        for (int it = 0; it < 32; it++) {          // 64n x 128k
            int idx = it * 256 + tid;
            int n = idx & 63, k = idx >> 6;
            uint32_t bits = cvt_tf32(whh[(size_t)(kbase + k) * NH + n0C + n]);
            int kk = k >> 3, pos = k & 7, ntile = n >> 3, g = n & 7;
            int lane = g * 4 + (pos & 3), half = pos >> 2;
            *(uint32_t*)((char*)BCf + ((size_t)(kk * 8 + ntile) * 32 + lane) * 8 + half * 4) = bits;
        }
    }
    gridbar_atomic();      // publishes resets + gamma + atf + weights
    unsigned gen = 0;

    const int kkset0[8] = {0, 1, 2, 3, 8, 9, 10, 11};
    const int kkset1[8] = {4, 5, 6, 7, 12, 13, 14, 15};

    for (int t = 0; t < NT; t++) {
        const unsigned tgt = 8u * (unsigned)(t + 1);

        // ---- prefetch P_h row for D and gamma(t+1) ----
        const float4* Pp = (const float4*)(g_P + ((size_t)(bid * NT + t)) * NH3);
        float4 phh = __ldg(Pp + 512 + tid);
        int tn = (t + 1 < NT) ? t + 1 : t;
        float4 gnv = __ldg((const float4*)(g_gamma + tn * NH) + tid);

        // ---- Phase A: zr partial = a @ [Whz|Whr] -> transposed store ----
        {
            FILL_WARP_STAGE(g_atf, 0);
            FILL_WARP_STAGE(g_atf, 1);

            float acc[2][8][4];
#pragma unroll
            for (int mt = 0; mt < 2; mt++)
#pragma unroll
                for (int nt = 0; nt < 8; nt++)
#pragma unroll
                    for (int c = 0; c < 4; c++) acc[mt][nt][c] = 0.f;

#pragma unroll
            for (int stg = 0; stg < 2; stg++) {
                if (stg == 0) CP_WAIT(1); else CP_WAIT(0);
                PAIR_BAR(pbar);
                const int* kks = stg == 0 ? kkset0 : kkset1;
#pragma unroll
                for (int q = 0; q < 8; q++) {
                    int kk = kks[q];
                    int k0 = kk * 8;
                    uint32_t a[2][4];
#pragma unroll
                    for (int mt = 0; mt < 2; mt++) {
                        const uint32_t* ap = As + (mbase + mt * 16 + gid) * STRA + k0 + tig;
                        a[mt][0] = ap[0];
                        a[mt][1] = ap[8 * STRA];
                        a[mt][2] = ap[4];
                        a[mt][3] = ap[8 * STRA + 4];
                    }
                    const ull* bp = BAf + (size_t)(kk * 16 + wn * 8) * 32 + lid;
#pragma unroll
                    for (int nt = 0; nt < 8; nt++) {
                        ull bbu = bp[nt * 32];
                        uint32_t b0 = (uint32_t)bbu, b1 = (uint32_t)(bbu >> 32);
                        MMA_TF32(acc[0][nt], a[0], b0, b1);
                        MMA_TF32(acc[1][nt], a[1], b0, b1);
                    }
                }
            }
            float* dstT = g_zrpartT[ksA];
#pragma unroll
            for (int mt = 0; mt < 2; mt++) {
                int m = mbase + mt * 16 + gid;
#pragma unroll
                for (int nt = 0; nt < 8; nt++) {
                    int n = n0A + wn * 64 + nt * 8 + tig * 2;
                    dstT[(size_t)n * 128 + m]           = acc[mt][nt][0];
                    dstT[(size_t)(n + 1) * 128 + m]     = acc[mt][nt][1];
                    dstT[(size_t)n * 128 + m + 8]       = acc[mt][nt][2];
                    dstT[(size_t)(n + 1) * 128 + m + 8] = acc[mt][nt][3];
                }
            }
        }
        cnt_arrive(&g_zrcnt[ntA * 32]);

        // ---- Phase B: reduce tile (ntB) x b-slice (bsB); gates ----
        {
            cnt_wait(&g_zrcnt[ntB * 32], tgt);
#pragma unroll
            for (int it = 0; it < 8; it++) {
                int c = it * 16 + c0B;
                float s = g_P[((size_t)(bb * NT) + t) * NH3 + ntB * 128 + c];
#pragma unroll
                for (int ks = 0; ks < 8; ks++)
                    s += g_zrpartT[ks][(size_t)(ntB * 128 + c) * 128 + bsB * 16 + (tid & 15)];
                if (ntB >= 8) {
                    int col = (ntB - 8) * 128 + c;
                    float aval = __uint_as_float(g_atf[bb * NH + col]);
                    g_ratf[bb * NH + col] = cvt_tf32(sigmf(s) * aval);
                } else {
                    g_z[bb * NH + ntB * 128 + c] = sigmf(s);
                }
            }
        }
        cnt_arrive(&g_rdone[ntB * 32]);

        // ---- Phase C: h~ partial = (r*a) @ Whh ----
        {
            cnt_wait(&g_rdone[(8 + ksC) * 32], tgt);

            FILL_WARP_STAGE(g_ratf, 0);
            FILL_WARP_STAGE(g_ratf, 1);

            float acc[2][4][4];
#pragma unroll
            for (int mt = 0; mt < 2; mt++)
#pragma unroll
                for (int nt = 0; nt < 4; nt++)
#pragma unroll
                    for (int c = 0; c < 4; c++) acc[mt][nt][c] = 0.f;

#pragma unroll
            for (int stg = 0; stg < 2; stg++) {
                if (stg == 0) CP_WAIT(1); else CP_WAIT(0);
                PAIR_BAR(pbar);
                const int* kks = stg == 0 ? kkset0 : kkset1;
#pragma unroll
                for (int q = 0; q < 8; q++) {
                    int kk = kks[q];
                    int k0 = kk * 8;
                    uint32_t a[2][4];
#pragma unroll
                    for (int mt = 0; mt < 2; mt++) {
                        const uint32_t* ap = As + (mbase + mt * 16 + gid) * STRA + k0 + tig;
                        a[mt][0] = ap[0];
                        a[mt][1] = ap[8 * STRA];
                        a[mt][2] = ap[4];
                        a[mt][3] = ap[8 * STRA + 4];
                    }
                    const ull* bp = BCf + (size_t)(kk * 8 + wn * 4) * 32 + lid;
#pragma unroll
                    for (int nt = 0; nt < 4; nt++) {
                        ull bbu = bp[nt * 32];
                        uint32_t b0 = (uint32_t)bbu, b1 = (uint32_t)(bbu >> 32);
                        MMA_TF32(acc[0][nt], a[0], b0, b1);
                        MMA_TF32(acc[1][nt], a[1], b0, b1);
                    }
                }
            }
            float* dst = g_hpart[ksC];
#pragma unroll
            for (int mt = 0; mt < 2; mt++) {
                int m = mbase + mt * 16 + gid;
#pragma unroll
                for (int nt = 0; nt < 4; nt++) {
                    int n = n0C + wn * 32 + nt * 8 + tig * 2;
                    *(float2*)&dst[m * NH + n] =
                        make_float2(acc[mt][nt][0], acc[mt][nt][1]);
                    *(float2*)&dst[(m + 8) * NH + n] =
                        make_float2(acc[mt][nt][2], acc[mt][nt][3]);
                }
            }
        }
        gridbar(++gen);

        // ---- Phase D: h update, output, next a ----
        {
            float4 sh = phh;
#pragma unroll
            for (int ks = 0; ks < 8; ks++) {
                const float4* hp = (const float4*)(g_hpart[ks] + bid * NH);
                float4 v = hp[tid];
                sh.x += v.x; sh.y += v.y; sh.z += v.z; sh.w += v.w;
            }
            float4 zz = *(const float4*)(g_z + bid * NH + tid * 4);
            float4 aa = a_reg;
            float4 hn;
            hn.x = (1.f - zz.x) * aa.x + zz.x * tanhf(sh.x);
            hn.y = (1.f - zz.y) * aa.y + zz.y * tanhf(sh.y);
            hn.z = (1.f - zz.z) * aa.z + zz.z * tanhf(sh.z);
            hn.w = (1.f - zz.w) * aa.w + zz.w * tanhf(sh.w);
            STG_CS4(out + ((size_t)(bid * NT + t)) * NH + tid * 4, hn);
            if (t + 1 < NT) {
                float4 an = make_float4(gnv.x * hn.x, gnv.y * hn.y, gnv.z * hn.z, gnv.w * hn.w);
                a_reg = an;
                uint4 u;
                u.x = cvt_tf32(an.x); u.y = cvt_tf32(an.y);
                u.z = cvt_tf32(an.z); u.w = cvt_tf32(an.w);
                *(uint4*)(g_atf + bid * NH + tid * 4) = u;
            } else {
                *(float4*)(hlast + bid * NH + tid * 4) = hn;
            }
        }
        gridbar(++gen);
    }
}

// ---------------- launch -----------------------------------------------------
extern "C" void kernel_launch(void* const* d_in, const int* in_sizes, int n_in,
                              void* d_out, int out_size) {
    const float* value = (const float*)d_in[0];
    const float* delta = (const float*)d_in[1];
    const float* wdg   = (const float*)d_in[2];
    const float* wxz   = (const float*)d_in[3];
    const float* whz   = (const float*)d_in[4];
    const float* wxr   = (const float*)d_in[5];
    const float* whr   = (const float*)d_in[6];
    const float* wxh   = (const float*)d_in[7];
    const float* whh   = (const float*)d_in[8];
    const float* bdg   = (const float*)d_in[9];
    const float* bz    = (const float*)d_in[10];
    const float* br    = (const float*)d_in[11];
    const float* bh    = (const float*)d_in[12];
    float* out = (float*)d_out;
    float* hlast = out + ((size_t)out_size - (size_t)NB * NH);

    cudaFuncSetAttribute(k_persist, cudaFuncAttributeMaxDynamicSharedMemorySize, SMEM_DYN);

    k_xproj<<<dim3(24, 512), 256>>>(value, wxz, wxr, wxh, bz, br, bh);
    k_persist<<<NBLK, NTHR, SMEM_DYN>>>(delta, wdg, bdg, whz, whr, whh, out, hlast);
}

// round 15
// speedup vs baseline: 1.6652x; 1.1651x over previous
#include <cuda_runtime.h>
#include <math.h>
#include <stdint.h>

typedef unsigned long long ull;

#define NB 128
#define ND 256
#define NH 1024
#define NT 512
#define NH3 3072
#define NBLK 128
#define NTHR 256

// ---------------- scratch (static device globals) ---------------------------
__device__ float    g_P[(size_t)NT * NB * NH3];   // x-projections (+bias)
__device__ float    g_gamma[NT * NH];
__device__ uint32_t g_atf[NB * NH];               // a = gamma*h, tf32 bits
__device__ uint32_t g_ratf[NB * NH];              // r*a, tf32 bits
__device__ float    g_zrpart[8][NB * 2 * NH];
__device__ float    g_hpart[8][NB * NH];

// ---------------- grid barriers ----------------------------------------------
__device__ unsigned g_bar_count = 0;
__device__ volatile unsigned g_bar_gen = 0;
__device__ unsigned g_flags[NBLK * 32];           // one 128B line per block

__device__ __forceinline__ void gridbar_atomic() {
    __syncthreads();
    if (threadIdx.x == 0) {
        unsigned gen = g_bar_gen;
        __threadfence();
        if (atomicAdd(&g_bar_count, 1) == NBLK - 1) {
            g_bar_count = 0;
            __threadfence();
            g_bar_gen = gen + 1;
        } else {
            while (g_bar_gen == gen) {}
            __threadfence();
        }
    }
    __syncthreads();
}

__device__ __forceinline__ void gridbar(unsigned gen) {
    __syncthreads();
    if (threadIdx.x == 0) {
        __threadfence();
        *(volatile unsigned*)&g_flags[blockIdx.x * 32] = gen;
    }
    if (threadIdx.x < NBLK) {
        while (*(volatile unsigned*)&g_flags[threadIdx.x * 32] < gen) {}
    }
    __threadfence();
    __syncthreads();
}

// ---------------- helpers ----------------------------------------------------
__device__ __forceinline__ float sigmf(float x) { return 1.f / (1.f + __expf(-x)); }

__device__ __forceinline__ uint32_t cvt_tf32(float x) {
    uint32_t r; asm("cvt.rna.tf32.f32 %0, %1;" : "=r"(r) : "f"(x)); return r;
}
__device__ __forceinline__ uint32_t smem_u32(const void* p) {
    uint32_t a;
    asm("{ .reg .u64 t; cvta.to.shared.u64 t, %1; cvt.u32.u64 %0, t; }" : "=r"(a) : "l"(p));
    return a;
}

#define MMA_TF32(d, a, b0, b1) \
    asm volatile("mma.sync.aligned.m16n8k8.row.col.f32.tf32.tf32.f32 " \
        "{%0,%1,%2,%3}, {%4,%5,%6,%7}, {%8,%9}, {%0,%1,%2,%3};" \
        : "+f"((d)[0]), "+f"((d)[1]), "+f"((d)[2]), "+f"((d)[3]) \
        : "r"((a)[0]), "r"((a)[1]), "r"((a)[2]), "r"((a)[3]), "r"(b0), "r"(b1))

#define CP_ASYNC16(dst_u32, src_ptr) \
    asm volatile("cp.async.cg.shared.global [%0], [%1], 16;" :: "r"(dst_u32), "l"(src_ptr) : "memory")
#define CP_COMMIT() asm volatile("cp.async.commit_group;" ::: "memory")
#define CP_WAIT(n)  asm volatile("cp.async.wait_group %0;" :: "n"(n) : "memory")

#define PAIR_BAR(id) asm volatile("bar.sync %0, 64;" :: "r"(id) : "memory")

#define STG_CS4(p, v) \
    asm volatile("st.global.cs.v4.f32 [%0], {%1,%2,%3,%4};" \
        :: "l"(p), "f"((v).x), "f"((v).y), "f"((v).z), "f"((v).w) : "memory")

// persist smem layout (bytes)
#define STRA      132                     // A row stride in 4B words
#define OFF_AS    0                       // 128*132*4 = 67584
#define OFF_BAF   67584                   // 16*16*32*8 = 65536
#define OFF_BCF   133120                  // 16*8*32*8  = 32768
#define SMEM_DYN  165888

// per-warp fill: warp covers its m-strip [mbase, mbase+32), k-quarter
// [wn*64 + s*32, +32). 8 float4 per lane per stage.
#define FILL_WARP_STAGE(src, s) \
    do { \
        _Pragma("unroll") \
        for (int i = 0; i < 8; i++) { \
            int e = i * 32 + lid; \
            int row = e >> 3, kq = e & 7; \
            int m = mbase + row; \
            int k = wn * 64 + (s) * 32 + kq * 4; \
            uint32_t d = sb + OFF_AS + (uint32_t)(m * STRA + k) * 4; \
            CP_ASYNC16(d, (const void*)((src) + (size_t)m * NH + kbase + k)); \
        } \
        CP_COMMIT(); \
    } while (0)

// ---------------- x-projection GEMM (tf32 MMA, vectorized, 2 CTAs/SM) --------
__global__ __launch_bounds__(256, 2) void k_xproj(
    const float* __restrict__ value,
    const float* __restrict__ wxz, const float* __restrict__ wxr,
    const float* __restrict__ wxh,
    const float* __restrict__ bbz, const float* __restrict__ bbr,
    const float* __restrict__ bbh)
{
    __shared__ uint32_t As[32 * 132];     // [k][m], stride 132
    __shared__ uint32_t Bs[128 * 36];     // [n][k], stride 36
    const int n0 = blockIdx.x * 128;
    const int m0 = blockIdx.y * 128;
    const int gate = n0 >> 10;
    const int j0 = n0 & (NH - 1);
    const float* W    = (gate == 0) ? wxz : (gate == 1 ? wxr : wxh);
    const float* bias = (gate == 0) ? bbz : (gate == 1 ? bbr : bbh);
    const int b  = m0 >> 9;
    const int t0 = m0 & (NT - 1);
    const int tid = threadIdx.x;
    const int wid = tid >> 5, lid = tid & 31;
    const int gid = lid >> 2, tig = lid & 3;
    const int mbase = (wid & 3) * 32;
    const int nstrip = (wid >> 2) * 64;

    float acc[2][8][4];
#pragma unroll
    for (int mt = 0; mt < 2; mt++)
#pragma unroll
        for (int nt = 0; nt < 8; nt++)
#pragma unroll
            for (int c = 0; c < 4; c++) acc[mt][nt][c] = 0.f;

    const float* Abase = value + (size_t)b * ND * NT + t0;

    for (int kc = 0; kc < ND; kc += 32) {
        // A: [k][m], m contiguous in gmem and smem -> float4 loads/stores
#pragma unroll
        for (int it = 0; it < 4; it++) {
            int idx = it * 256 + tid;
            int m4 = idx & 31, k = idx >> 5;
            float4 v = __ldg((const float4*)(Abase + (size_t)(kc + k) * NT) + m4);
            uint4 w;
            w.x = cvt_tf32(v.x); w.y = cvt_tf32(v.y);
            w.z = cvt_tf32(v.z); w.w = cvt_tf32(v.w);
            *(uint4*)&As[k * 132 + m4 * 4] = w;
        }
        // B: read float4 along n (contiguous), scatter into [n][k]
#pragma unroll
        for (int it = 0; it < 4; it++) {
            int idx = it * 256 + tid;
            int n4 = idx & 31, k = idx >> 5;
            float4 v = __ldg((const float4*)(W + (size_t)(kc + k) * NH + j0) + n4);
            int n = n4 * 4;
            Bs[n * 36 + k]       = cvt_tf32(v.x);
            Bs[(n + 1) * 36 + k] = cvt_tf32(v.y);
            Bs[(n + 2) * 36 + k] = cvt_tf32(v.z);
            Bs[(n + 3) * 36 + k] = cvt_tf32(v.w);
        }
        __syncthreads();
#pragma unroll
        for (int kk = 0; kk < 4; kk++) {
            int k0 = kk * 8;
            uint32_t a[2][4];
#pragma unroll
            for (int mt = 0; mt < 2; mt++) {
                int m = mbase + mt * 16 + gid;
                a[mt][0] = As[(k0 + tig) * 132 + m];
                a[mt][1] = As[(k0 + tig) * 132 + m + 8];
                a[mt][2] = As[(k0 + tig + 4) * 132 + m];
                a[mt][3] = As[(k0 + tig + 4) * 132 + m + 8];
            }
#pragma unroll
            for (int nt = 0; nt < 8; nt++) {
                int n = nstrip + nt * 8 + gid;
                uint32_t b0 = Bs[n * 36 + k0 + tig];
                uint32_t b1 = Bs[n * 36 + k0 + tig + 4];
                MMA_TF32(acc[0][nt], a[0], b0, b1);
                MMA_TF32(acc[1][nt], a[1], b0, b1);
            }
        }
        __syncthreads();
    }
#pragma unroll
    for (int mt = 0; mt < 2; mt++) {
        int m = m0 + mbase + mt * 16 + gid;
#pragma unroll
        for (int nt = 0; nt < 8; nt++) {
            int nl = nstrip + nt * 8 + tig * 2;
            float b0v = bias[j0 + nl], b1v = bias[j0 + nl + 1];
            float* dst = g_P + (size_t)m * NH3 + n0 + nl;
            *(float2*)dst = make_float2(acc[mt][nt][0] + b0v, acc[mt][nt][1] + b1v);
            float* dst2 = g_P + (size_t)(m + 8) * NH3 + n0 + nl;
            *(float2*)dst2 = make_float2(acc[mt][nt][2] + b0v, acc[mt][nt][3] + b1v);
        }
    }
}

// ---------------- persistent recurrence kernel (round-12 base + micro) -------
__global__ __launch_bounds__(NTHR, 1) void k_persist(
    const float* __restrict__ delta,
    const float* __restrict__ wdg, const float* __restrict__ bdg,
    const float* __restrict__ whz, const float* __restrict__ whr,
    const float* __restrict__ whh,
    float* __restrict__ out, float* __restrict__ hlast)
{
    extern __shared__ char smem[];
    const uint32_t sb = smem_u32(smem);
    uint32_t* As  = (uint32_t*)(smem + OFF_AS);   // [m128][k128] stride 132
    ull* BAf      = (ull*)(smem + OFF_BAF);       // frag order [kk16][ntile16][lid32]
    ull* BCf      = (ull*)(smem + OFF_BCF);       // frag order [kk16][ntile8][lid32]

    const int bid = blockIdx.x;
    const int tid = threadIdx.x;
    const int wid = tid >> 5;
    const int lid = tid & 31;
    const int gid = lid >> 2, tig = lid & 3;
    const int mbase = (wid & 3) * 32;
    const int wn    = wid >> 2;             // 0..1
    const int pbar  = 1 + (wid & 3);        // named pair-barrier id (warps w, w+4)

    // block roles
    const int n0A    = (bid >> 3) * 128;    // zr: N base (0..2047)
    const int ksA    = bid & 7;
    const int kbase  = ksA * 128;           // shared k-slice for A and C
    const int gate   = n0A >> 10;
    const int j0     = n0A & (NH - 1);
    const int n0C    = (bid >> 3) * 64;     // h~: N base (0..1023)
    const int ksC    = bid & 7;

    // ---- prologue: flag reset, gamma, zero state ----
    if (tid == 0) *(volatile unsigned*)&g_flags[bid * 32] = 0;

    for (int it = 0; it < 4; it++) {
        int idx4 = bid * 1024 + it * 256 + tid;
        int i = idx4 * 4;
        int t = i >> 10, j = i & (NH - 1);
        float d = delta[t];
        float4 w = *(const float4*)(wdg + j);
        float4 bb = *(const float4*)(bdg + j);
        float4 g;
        g.x = expf(-fmaxf(0.f, w.x * d + bb.x));
        g.y = expf(-fmaxf(0.f, w.y * d + bb.y));
        g.z = expf(-fmaxf(0.f, w.z * d + bb.z));
        g.w = expf(-fmaxf(0.f, w.w * d + bb.w));
        *(float4*)(g_gamma + i) = g;
    }
    float4 a_reg = make_float4(0.f, 0.f, 0.f, 0.f);
    *(uint4*)(g_atf + bid * NH + tid * 4) = make_uint4(0u, 0u, 0u, 0u);

    // ---- prologue: stationary weights -> fragment-order smem (tf32) ----
    {
        const float* Wzr = gate ? whr : whz;
#pragma unroll 1
        for (int it = 0; it < 64; it++) {          // 128n x 128k
            int idx = it * 256 + tid;
            int n = idx & 127, k = idx >> 7;
            uint32_t bits = cvt_tf32(Wzr[(size_t)(kbase + k) * NH + j0 + n]);
            int kk = k >> 3, pos = k & 7, ntile = n >> 3, g = n & 7;
            int lane = g * 4 + (pos & 3), half = pos >> 2;
            *(uint32_t*)((char*)BAf + ((size_t)(kk * 16 + ntile) * 32 + lane) * 8 + half * 4) = bits;
        }
#pragma unroll 1
        for (int it = 0; it < 32; it++) {          // 64n x 128k
            int idx = it * 256 + tid;
            int n = idx & 63, k = idx >> 6;
            uint32_t bits = cvt_tf32(whh[(size_t)(kbase + k) * NH + n0C + n]);
            int kk = k >> 3, pos = k & 7, ntile = n >> 3, g = n & 7;
            int lane = g * 4 + (pos & 3), half = pos >> 2;
            *(uint32_t*)((char*)BCf + ((size_t)(kk * 8 + ntile) * 32 + lane) * 8 + half * 4) = bits;
        }
    }
    gridbar_atomic();      // publishes flag reset + gamma + atf + weights
    unsigned gen = 0;

    // kk visit order: first pair-stage covers kk {0-3, 8-11}, second the rest
    const int kkset0[8] = {0, 1, 2, 3, 8, 9, 10, 11};
    const int kkset1[8] = {4, 5, 6, 7, 12, 13, 14, 15};

    for (int t = 0; t < NT; t++) {
        // ---- prefetch P rows (B, D) and gamma(t+1) ----
        const float4* Pp = (const float4*)(g_P + ((size_t)(bid * NT + t)) * NH3);
        float4 pz  = __ldg(Pp + tid);
        float4 pr  = __ldg(Pp + 256 + tid);
        float4 phh = __ldg(Pp + 512 + tid);
        int tn = (t + 1 < NT) ? t + 1 : t;
        float4 gn = __ldg((const float4*)(g_gamma + tn * NH) + tid);

        float4 sz_c;   // pre-sigmoid z, carried B -> D in registers

        // ---- Phase A: zr partial = a @ [Whz|Whr]  (M128,N128,K128) ----
        {
            FILL_WARP_STAGE(g_atf, 0);
            FILL_WARP_STAGE(g_atf, 1);

            float acc[2][8][4];
#pragma unroll
            for (int mt = 0; mt < 2; mt++)
#pragma unroll
                for (int nt = 0; nt < 8; nt++)
#pragma unroll
                    for (int c = 0; c < 4; c++) acc[mt][nt][c] = 0.f;

#pragma unroll
            for (int stg = 0; stg < 2; stg++) {
                if (stg == 0) CP_WAIT(1); else CP_WAIT(0);
                PAIR_BAR(pbar);
                const int* kks = stg == 0 ? kkset0 : kkset1;
#pragma unroll
                for (int q = 0; q < 8; q++) {
                    int kk = kks[q];
                    int k0 = kk * 8;
                    uint32_t a[2][4];
#pragma unroll
                    for (int mt = 0; mt < 2; mt++) {
                        const uint32_t* ap = As + (mbase + mt * 16 + gid) * STRA + k0 + tig;
                        a[mt][0] = ap[0];
                        a[mt][1] = ap[8 * STRA];
                        a[mt][2] = ap[4];
                        a[mt][3] = ap[8 * STRA + 4];
                    }
                    const ull* bp = BAf + (size_t)(kk * 16 + wn * 8) * 32 + lid;
#pragma unroll
                    for (int nt = 0; nt < 8; nt++) {
                        ull bb = bp[nt * 32];
                        uint32_t b0 = (uint32_t)bb, b1 = (uint32_t)(bb >> 32);
                        MMA_TF32(acc[0][nt], a[0], b0, b1);
                        MMA_TF32(acc[1][nt], a[1], b0, b1);
                    }
                }
            }
            float* dst = g_zrpart[ksA];
#pragma unroll
            for (int mt = 0; mt < 2; mt++) {
                int m = mbase + mt * 16 + gid;
#pragma unroll
                for (int nt = 0; nt < 8; nt++) {
                    int n = n0A + wn * 64 + nt * 8 + tig * 2;
                    *(float2*)&dst[m * (2 * NH) + n] =
                        make_float2(acc[mt][nt][0], acc[mt][nt][1]);
                    *(float2*)&dst[(m + 8) * (2 * NH) + n] =
                        make_float2(acc[mt][nt][2], acc[mt][nt][3]);
                }
            }
        }
        gridbar(++gen);

        // ---- Phase B: r gate + ra(tf32) -> global; z pre-act kept in regs ----
        {
            float4 sz = pz, sr = pr;
#pragma unroll
            for (int ks = 0; ks < 8; ks++) {
                const float4* zp = (const float4*)(g_zrpart[ks] + bid * 2 * NH);
                float4 v = zp[tid];
                sz.x += v.x; sz.y += v.y; sz.z += v.z; sz.w += v.w;
                float4 w = zp[256 + tid];
                sr.x += w.x; sr.y += w.y; sr.z += w.z; sr.w += w.w;
            }
            sz_c = sz;
            float4 rf = make_float4(sigmf(sr.x), sigmf(sr.y), sigmf(sr.z), sigmf(sr.w));
            uint4 u;
            u.x = cvt_tf32(rf.x * a_reg.x);
            u.y = cvt_tf32(rf.y * a_reg.y);
            u.z = cvt_tf32(rf.z * a_reg.z);
            u.w = cvt_tf32(rf.w * a_reg.w);
            *(uint4*)(g_ratf + bid * NH + tid * 4) = u;
        }
        gridbar(++gen);

        // ---- Phase C: h~ partial = (r*a) @ Whh  (M128,N64,K128) ----
        {
            FILL_WARP_STAGE(g_ratf, 0);
            FILL_WARP_STAGE(g_ratf, 1);

            float acc[2][4][4];
#pragma unroll
            for (int mt = 0; mt < 2; mt++)
#pragma unroll
                for (int nt = 0; nt < 4; nt++)
#pragma unroll
                    for (int c = 0; c < 4; c++) acc[mt][nt][c] = 0.f;

#pragma unroll
            for (int stg = 0; stg < 2; stg++) {
                if (stg == 0) CP_WAIT(1); else CP_WAIT(0);
                PAIR_BAR(pbar);
                const int* kks = stg == 0 ? kkset0 : kkset1;
#pragma unroll
                for (int q = 0; q < 8; q++) {
                    int kk = kks[q];
                    int k0 = kk * 8;
                    uint32_t a[2][4];
#pragma unroll
                    for (int mt = 0; mt < 2; mt++) {
                        const uint32_t* ap = As + (mbase + mt * 16 + gid) * STRA + k0 + tig;
                        a[mt][0] = ap[0];
                        a[mt][1] = ap[8 * STRA];
                        a[mt][2] = ap[4];
                        a[mt][3] = ap[8 * STRA + 4];
                    }
                    const ull* bp = BCf + (size_t)(kk * 8 + wn * 4) * 32 + lid;
#pragma unroll
                    for (int nt = 0; nt < 4; nt++) {
                        ull bb = bp[nt * 32];
                        uint32_t b0 = (uint32_t)bb, b1 = (uint32_t)(bb >> 32);
                        MMA_TF32(acc[0][nt], a[0], b0, b1);
                        MMA_TF32(acc[1][nt], a[1], b0, b1);
                    }
                }
            }
            float* dst = g_hpart[ksC];
#pragma unroll
            for (int mt = 0; mt < 2; mt++) {
                int m = mbase + mt * 16 + gid;
#pragma unroll
                for (int nt = 0; nt < 4; nt++) {
                    int n = n0C + wn * 32 + nt * 8 + tig * 2;
                    *(float2*)&dst[m * NH + n] =
                        make_float2(acc[mt][nt][0], acc[mt][nt][1]);
                    *(float2*)&dst[(m + 8) * NH + n] =
                        make_float2(acc[mt][nt][2], acc[mt][nt][3]);
                }
            }
        }
        gridbar(++gen);

        // ---- Phase D: h update; publish atf first, then stream out ----
        {
            float4 sh = phh;
#pragma unroll
            for (int ks = 0; ks < 8; ks++) {
                const float4* hp = (const float4*)(g_hpart[ks] + bid * NH);
                float4 v = hp[tid];
                sh.x += v.x; sh.y += v.y; sh.z += v.z; sh.w += v.w;
            }
            float4 zz = make_float4(sigmf(sz_c.x), sigmf(sz_c.y),
                                    sigmf(sz_c.z), sigmf(sz_c.w));
            float4 aa = a_reg;
            float4 hn;
            hn.x = (1.f - zz.x) * aa.x + zz.x * tanhf(sh.x);
            hn.y = (1.f - zz.y) * aa.y + zz.y * tanhf(sh.y);
            hn.z = (1.f - zz.z) * aa.z + zz.z * tanhf(sh.z);
            hn.w = (1.f - zz.w) * aa.w + zz.w * tanhf(sh.w);
            if (t + 1 < NT) {
                float4 an = make_float4(gn.x * hn.x, gn.y * hn.y, gn.z * hn.z, gn.w * hn.w);
                a_reg = an;
                uint4 u;
                u.x = cvt_tf32(an.x); u.y = cvt_tf32(an.y);
                u.z = cvt_tf32(an.z); u.w = cvt_tf32(an.w);
                *(uint4*)(g_atf + bid * NH + tid * 4) = u;   // publish first
            } else {
                *(float4*)(hlast + bid * NH + tid * 4) = hn;
            }
            STG_CS4(out + ((size_t)(bid * NT + t)) * NH + tid * 4, hn);
        }
        gridbar(++gen);
    }
}

// ---------------- launch -----------------------------------------------------
extern "C" void kernel_launch(void* const* d_in, const int* in_sizes, int n_in,
                              void* d_out, int out_size) {
    const float* value = (const float*)d_in[0];
    const float* delta = (const float*)d_in[1];
    const float* wdg   = (const float*)d_in[2];
    const float* wxz   = (const float*)d_in[3];
    const float* whz   = (const float*)d_in[4];
    const float* wxr   = (const float*)d_in[5];
    const float* whr   = (const float*)d_in[6];
    const float* wxh   = (const float*)d_in[7];
    const float* whh   = (const float*)d_in[8];
    const float* bdg   = (const float*)d_in[9];
    const float* bz    = (const float*)d_in[10];
    const float* br    = (const float*)d_in[11];
    const float* bh    = (const float*)d_in[12];
    float* out = (float*)d_out;
    float* hlast = out + ((size_t)out_size - (size_t)NB * NH);

    cudaFuncSetAttribute(k_persist, cudaFuncAttributeMaxDynamicSharedMemorySize, SMEM_DYN);

    k_xproj<<<dim3(24, 512), 256>>>(value, wxz, wxr, wxh, bz, br, bh);
    k_persist<<<NBLK, NTHR, SMEM_DYN>>>(delta, wdg, bdg, whz, whr, whh, out, hlast);
}

// round 16
// speedup vs baseline: 1.7805x; 1.0693x over previous
#include <cuda_runtime.h>
#include <math.h>
#include <stdint.h>

typedef unsigned long long ull;

#define NB 128
#define ND 256
#define NH 1024
#define NT 512
#define NH3 3072
#define NBLK 128
#define NTHR 256

// ---------------- scratch (static device globals) ---------------------------
__device__ float    g_P[(size_t)NT * NB * NH3];   // x-projections (+bias)
__device__ float    g_gamma[NT * NH];
__device__ uint32_t g_atf[NB * NH];               // a = gamma*h, tf32 bits
__device__ uint32_t g_ratf[NB * NH];              // r*a, tf32 bits
__device__ float    g_z[NB * NH];                 // z gates
__device__ float    g_zrpart[8][NB * 2 * NH];
__device__ float    g_hpart[8][NB * NH];

// ---------------- sync objects ------------------------------------------------
__device__ unsigned g_bar_count = 0;
__device__ volatile unsigned g_bar_gen = 0;
__device__ unsigned g_flags[NBLK * 32];           // per-block 128B line
__device__ unsigned g_zrcnt[16 * 32];             // per zr-n-tile producer counter
__device__ unsigned g_rdone[16 * 32];             // per zr-n-tile gate-done counter

__device__ __forceinline__ void gridbar_atomic() {
    __syncthreads();
    if (threadIdx.x == 0) {
        unsigned gen = g_bar_gen;
        __threadfence();
        if (atomicAdd(&g_bar_count, 1) == NBLK - 1) {
            g_bar_count = 0;
            __threadfence();
            g_bar_gen = gen + 1;
        } else {
            while (g_bar_gen == gen) {}
            __threadfence();
        }
    }
    __syncthreads();
}

__device__ __forceinline__ void gridbar(unsigned gen) {
    __syncthreads();
    if (threadIdx.x == 0) {
        __threadfence();
        *(volatile unsigned*)&g_flags[blockIdx.x * 32] = gen;
    }
    if (threadIdx.x < NBLK) {
        while (*(volatile unsigned*)&g_flags[threadIdx.x * 32] < gen) {}
    }
    __threadfence();
    __syncthreads();
}

#define RED_ADD1(p) \
    asm volatile("red.global.add.u32 [%0], %1;" :: "l"(p), "r"(1u) : "memory")

__device__ __forceinline__ void cnt_arrive(unsigned* cnt) {
    __syncthreads();
    if (threadIdx.x == 0) { __threadfence(); RED_ADD1(cnt); }
}
__device__ __forceinline__ void cnt_wait(unsigned* cnt, unsigned target) {
    if (threadIdx.x == 0) {
        while (*(volatile unsigned*)cnt < target) {}
        __threadfence();
    }
    __syncthreads();
}

// ---------------- helpers ----------------------------------------------------
__device__ __forceinline__ float sigmf(float x) { return 1.f / (1.f + __expf(-x)); }

__device__ __forceinline__ uint32_t cvt_tf32(float x) {
    uint32_t r; asm("cvt.rna.tf32.f32 %0, %1;" : "=r"(r) : "f"(x)); return r;
}
__device__ __forceinline__ uint32_t smem_u32(const void* p) {
    uint32_t a;
    asm("{ .reg .u64 t; cvta.to.shared.u64 t, %1; cvt.u32.u64 %0, t; }" : "=r"(a) : "l"(p));
    return a;
}

#define MMA_TF32(d, a, b0, b1) \
    asm volatile("mma.sync.aligned.m16n8k8.row.col.f32.tf32.tf32.f32 " \
        "{%0,%1,%2,%3}, {%4,%5,%6,%7}, {%8,%9}, {%0,%1,%2,%3};" \
        : "+f"((d)[0]), "+f"((d)[1]), "+f"((d)[2]), "+f"((d)[3]) \
        : "r"((a)[0]), "r"((a)[1]), "r"((a)[2]), "r"((a)[3]), "r"(b0), "r"(b1))

#define CP_ASYNC16(dst_u32, src_ptr) \
    asm volatile("cp.async.cg.shared.global [%0], [%1], 16;" :: "r"(dst_u32), "l"(src_ptr) : "memory")
#define CP_COMMIT() asm volatile("cp.async.commit_group;" ::: "memory")
#define CP_WAIT(n)  asm volatile("cp.async.wait_group %0;" :: "n"(n) : "memory")

#define PAIR_BAR(id) asm volatile("bar.sync %0, 64;" :: "r"(id) : "memory")

#define STG_CS4(p, v) \
    asm volatile("st.global.cs.v4.f32 [%0], {%1,%2,%3,%4};" \
        :: "l"(p), "f"((v).x), "f"((v).y), "f"((v).z), "f"((v).w) : "memory")

// persist smem layout (bytes)
#define STRA      132
#define OFF_AS    0
#define OFF_BAF   67584
#define OFF_BCF   133120
#define SMEM_DYN  165888

#define FILL_WARP_STAGE(src, s) \
    do { \
        _Pragma("unroll") \
        for (int i = 0; i < 8; i++) { \
            int e = i * 32 + lid; \
            int row = e >> 3, kq = e & 7; \
            int m = mbase + row; \
            int k = wn * 64 + (s) * 32 + kq * 4; \
            uint32_t d = sb + OFF_AS + (uint32_t)(m * STRA + k) * 4; \
            CP_ASYNC16(d, (const void*)((src) + (size_t)m * NH + kbase + k)); \
        } \
        CP_COMMIT(); \
    } while (0)

// ---------------- x-projection GEMM (tf32 MMA, vectorized, 2 CTAs/SM) --------
__global__ __launch_bounds__(256, 2) void k_xproj(
    const float* __restrict__ value,
    const float* __restrict__ wxz, const float* __restrict__ wxr,
    const float* __restrict__ wxh,
    const float* __restrict__ bbz, const float* __restrict__ bbr,
    const float* __restrict__ bbh)
{
    __shared__ uint32_t As[32 * 132];
    __shared__ uint32_t Bs[128 * 36];
    const int n0 = blockIdx.x * 128;
    const int m0 = blockIdx.y * 128;
    const int gate = n0 >> 10;
    const int j0 = n0 & (NH - 1);
    const float* W    = (gate == 0) ? wxz : (gate == 1 ? wxr : wxh);
    const float* bias = (gate == 0) ? bbz : (gate == 1 ? bbr : bbh);
    const int b  = m0 >> 9;
    const int t0 = m0 & (NT - 1);
    const int tid = threadIdx.x;
    const int wid = tid >> 5, lid = tid & 31;
    const int gid = lid >> 2, tig = lid & 3;
    const int mbase = (wid & 3) * 32;
    const int nstrip = (wid >> 2) * 64;

    float acc[2][8][4];
#pragma unroll
    for (int mt = 0; mt < 2; mt++)
#pragma unroll
        for (int nt = 0; nt < 8; nt++)
#pragma unroll
            for (int c = 0; c < 4; c++) acc[mt][nt][c] = 0.f;

    const float* Abase = value + (size_t)b * ND * NT + t0;

    for (int kc = 0; kc < ND; kc += 32) {
#pragma unroll
        for (int it = 0; it < 4; it++) {
            int idx = it * 256 + tid;
            int m4 = idx & 31, k = idx >> 5;
            float4 v = __ldg((const float4*)(Abase + (size_t)(kc + k) * NT) + m4);
            uint4 w;
            w.x = cvt_tf32(v.x); w.y = cvt_tf32(v.y);
            w.z = cvt_tf32(v.z); w.w = cvt_tf32(v.w);
            *(uint4*)&As[k * 132 + m4 * 4] = w;
        }
#pragma unroll
        for (int it = 0; it < 4; it++) {
            int idx = it * 256 + tid;
            int n4 = idx & 31, k = idx >> 5;
            float4 v = __ldg((const float4*)(W + (size_t)(kc + k) * NH + j0) + n4);
            int n = n4 * 4;
            Bs[n * 36 + k]       = cvt_tf32(v.x);
            Bs[(n + 1) * 36 + k] = cvt_tf32(v.y);
            Bs[(n + 2) * 36 + k] = cvt_tf32(v.z);
            Bs[(n + 3) * 36 + k] = cvt_tf32(v.w);
        }
        __syncthreads();
#pragma unroll
        for (int kk = 0; kk < 4; kk++) {
            int k0 = kk * 8;
            uint32_t a[2][4];
#pragma unroll
            for (int mt = 0; mt < 2; mt++) {
                int m = mbase + mt * 16 + gid;
                a[mt][0] = As[(k0 + tig) * 132 + m];
                a[mt][1] = As[(k0 + tig) * 132 + m + 8];
                a[mt][2] = As[(k0 + tig + 4) * 132 + m];
                a[mt][3] = As[(k0 + tig + 4) * 132 + m + 8];
            }
#pragma unroll
            for (int nt = 0; nt < 8; nt++) {
                int n = nstrip + nt * 8 + gid;
                uint32_t b0 = Bs[n * 36 + k0 + tig];
                uint32_t b1 = Bs[n * 36 + k0 + tig + 4];
                MMA_TF32(acc[0][nt], a[0], b0, b1);
                MMA_TF32(acc[1][nt], a[1], b0, b1);
            }
        }
        __syncthreads();
    }
#pragma unroll
    for (int mt = 0; mt < 2; mt++) {
        int m = m0 + mbase + mt * 16 + gid;
#pragma unroll
        for (int nt = 0; nt < 8; nt++) {
            int nl = nstrip + nt * 8 + tig * 2;
            float b0v = bias[j0 + nl], b1v = bias[j0 + nl + 1];
            float* dst = g_P + (size_t)m * NH3 + n0 + nl;
            *(float2*)dst = make_float2(acc[mt][nt][0] + b0v, acc[mt][nt][1] + b1v);
            float* dst2 = g_P + (size_t)(m + 8) * NH3 + n0 + nl;
            *(float2*)dst2 = make_float2(acc[mt][nt][2] + b0v, acc[mt][nt][3] + b1v);
        }
    }
}

// ---------------- persistent recurrence (2 gridbars + 2 local waits) ---------
__global__ __launch_bounds__(NTHR, 1) void k_persist(
    const float* __restrict__ delta,
    const float* __restrict__ wdg, const float* __restrict__ bdg,
    const float* __restrict__ whz, const float* __restrict__ whr,
    const float* __restrict__ whh,
    float* __restrict__ out, float* __restrict__ hlast)
{
    extern __shared__ char smem[];
    const uint32_t sb = smem_u32(smem);
    uint32_t* As  = (uint32_t*)(smem + OFF_AS);
    ull* BAf      = (ull*)(smem + OFF_BAF);
    ull* BCf      = (ull*)(smem + OFF_BCF);

    const int bid = blockIdx.x;
    const int tid = threadIdx.x;
    const int wid = tid >> 5;
    const int lid = tid & 31;
    const int gid = lid >> 2, tig = lid & 3;
    const int mbase = (wid & 3) * 32;
    const int wn    = wid >> 2;
    const int pbar  = 1 + (wid & 3);

    // block roles
    const int ntA    = bid >> 3;            // zr n-tile (0..15); also B's tile
    const int ksA    = bid & 7;             // k-slice; also B's row-slice
    const int n0A    = ntA * 128;
    const int kbase  = ksA * 128;
    const int gate   = n0A >> 10;
    const int j0     = n0A & (NH - 1);
    const int n0C    = (bid >> 3) * 64;
    const int ksC    = bid & 7;

    // B-phase thread mapping: 16 rows x 32 float4-cols
    const int rowB = ksA * 16 + (tid >> 4);
    const int c4   = tid & 15;              // float4 col, chunks c4 and c4+16

    // ---- prologue: resets, gamma, zero state ----
    if (tid == 0) {
        *(volatile unsigned*)&g_flags[bid * 32] = 0;
        if (bid < 16) {
            *(volatile unsigned*)&g_zrcnt[bid * 32] = 0;
            *(volatile unsigned*)&g_rdone[bid * 32] = 0;
        }
    }

    for (int it = 0; it < 4; it++) {
        int idx4 = bid * 1024 + it * 256 + tid;
        int i = idx4 * 4;
        int t = i >> 10, j = i & (NH - 1);
        float d = delta[t];
        float4 w = *(const float4*)(wdg + j);
        float4 bb = *(const float4*)(bdg + j);
        float4 g;
        g.x = expf(-fmaxf(0.f, w.x * d + bb.x));
        g.y = expf(-fmaxf(0.f, w.y * d + bb.y));
        g.z = expf(-fmaxf(0.f, w.z * d + bb.z));
        g.w = expf(-fmaxf(0.f, w.w * d + bb.w));
        *(float4*)(g_gamma + i) = g;
    }
    float4 a_reg = make_float4(0.f, 0.f, 0.f, 0.f);
    *(uint4*)(g_atf + bid * NH + tid * 4) = make_uint4(0u, 0u, 0u, 0u);

    // ---- prologue: stationary weights -> fragment-order smem (tf32) ----
    {
        const float* Wzr = gate ? whr : whz;
#pragma unroll 1
        for (int it = 0; it < 64; it++) {
            int idx = it * 256 + tid;
            int n = idx & 127, k = idx >> 7;
            uint32_t bits = cvt_tf32(Wzr[(size_t)(kbase + k) * NH + j0 + n]);
            int kk = k >> 3, pos = k & 7, ntile = n >> 3, g = n & 7;
            int lane = g * 4 + (pos & 3), half = pos >> 2;
            *(uint32_t*)((char*)BAf + ((size_t)(kk * 16 + ntile) * 32 + lane) * 8 + half * 4) = bits;
        }
#pragma unroll 1
        for (int it = 0; it < 32; it++) {
            int idx = it * 256 + tid;
            int n = idx & 63, k = idx >> 6;
            uint32_t bits = cvt_tf32(whh[(size_t)(kbase + k) * NH + n0C + n]);
            int kk = k >> 3, pos = k & 7, ntile = n >> 3, g = n & 7;
            int lane = g * 4 + (pos & 3), half = pos >> 2;
            *(uint32_t*)((char*)BCf + ((size_t)(kk * 8 + ntile) * 32 + lane) * 8 + half * 4) = bits;
        }
    }
    gridbar_atomic();
    unsigned gen = 0;

    const int kkset0[8] = {0, 1, 2, 3, 8, 9, 10, 11};
    const int kkset1[8] = {4, 5, 6, 7, 12, 13, 14, 15};

    for (int t = 0; t < NT; t++) {
        const unsigned tgt = 8u * (unsigned)(t + 1);

        // ---- prefetch: P rows for B slice, P_h row + gamma(t+1) for D ----
        const float4* PB = (const float4*)(g_P + ((size_t)(rowB * NT + t)) * NH3 + n0A);
        float4 pb0 = __ldg(PB + c4);
        float4 pb1 = __ldg(PB + c4 + 16);
        const float4* Pp = (const float4*)(g_P + ((size_t)(bid * NT + t)) * NH3);
        float4 phh = __ldg(Pp + 512 + tid);
        int tn = (t + 1 < NT) ? t + 1 : t;
        float4 gn = __ldg((const float4*)(g_gamma + tn * NH) + tid);

        // ---- Phase A: zr partial = a @ [Whz|Whr] ----
        {
            FILL_WARP_STAGE(g_atf, 0);
            FILL_WARP_STAGE(g_atf, 1);

            float acc[2][8][4];
#pragma unroll
            for (int mt = 0; mt < 2; mt++)
#pragma unroll
                for (int nt = 0; nt < 8; nt++)
#pragma unroll
                    for (int c = 0; c < 4; c++) acc[mt][nt][c] = 0.f;

#pragma unroll
            for (int stg = 0; stg < 2; stg++) {
                if (stg == 0) CP_WAIT(1); else CP_WAIT(0);
                PAIR_BAR(pbar);
                const int* kks = stg == 0 ? kkset0 : kkset1;
#pragma unroll
                for (int q = 0; q < 8; q++) {
                    int kk = kks[q];
                    int k0 = kk * 8;
                    uint32_t a[2][4];
#pragma unroll
                    for (int mt = 0; mt < 2; mt++) {
                        const uint32_t* ap = As + (mbase + mt * 16 + gid) * STRA + k0 + tig;
                        a[mt][0] = ap[0];
                        a[mt][1] = ap[8 * STRA];
                        a[mt][2] = ap[4];
                        a[mt][3] = ap[8 * STRA + 4];
                    }
                    const ull* bp = BAf + (size_t)(kk * 16 + wn * 8) * 32 + lid;
#pragma unroll
                    for (int nt = 0; nt < 8; nt++) {
                        ull bb = bp[nt * 32];
                        uint32_t b0 = (uint32_t)bb, b1 = (uint32_t)(bb >> 32);
                        MMA_TF32(acc[0][nt], a[0], b0, b1);
                        MMA_TF32(acc[1][nt], a[1], b0, b1);
                    }
                }
            }
            float* dst = g_zrpart[ksA];
#pragma unroll
            for (int mt = 0; mt < 2; mt++) {
                int m = mbase + mt * 16 + gid;
#pragma unroll
                for (int nt = 0; nt < 8; nt++) {
                    int n = n0A + wn * 64 + nt * 8 + tig * 2;
                    *(float2*)&dst[m * (2 * NH) + n] =
                        make_float2(acc[mt][nt][0], acc[mt][nt][1]);
                    *(float2*)&dst[(m + 8) * (2 * NH) + n] =
                        make_float2(acc[mt][nt][2], acc[mt][nt][3]);
                }
            }
        }
        cnt_arrive(&g_zrcnt[ntA * 32]);

        // ---- Phase B: gates for tile ntA, rows [ksA*16, +16) ----
        {
            cnt_wait(&g_zrcnt[ntA * 32], tgt);
            float4 s0 = pb0, s1 = pb1;
#pragma unroll
            for (int ks = 0; ks < 8; ks++) {
                const float4* zp = (const float4*)(g_zrpart[ks] + rowB * 2 * NH + n0A);
                float4 v0 = zp[c4];
                s0.x += v0.x; s0.y += v0.y; s0.z += v0.z; s0.w += v0.w;
                float4 v1 = zp[c4 + 16];
                s1.x += v1.x; s1.y += v1.y; s1.z += v1.z; s1.w += v1.w;
            }
            if (ntA >= 8) {
                int colb = (ntA - 8) * 128;
                uint4 a0 = *(const uint4*)(g_atf + rowB * NH + colb + c4 * 4);
                uint4 a1 = *(const uint4*)(g_atf + rowB * NH + colb + (c4 + 16) * 4);
                uint4 u0, u1;
                u0.x = cvt_tf32(sigmf(s0.x) * __uint_as_float(a0.x));
                u0.y = cvt_tf32(sigmf(s0.y) * __uint_as_float(a0.y));
                u0.z = cvt_tf32(sigmf(s0.z) * __uint_as_float(a0.z));
                u0.w = cvt_tf32(sigmf(s0.w) * __uint_as_float(a0.w));
                u1.x = cvt_tf32(sigmf(s1.x) * __uint_as_float(a1.x));
                u1.y = cvt_tf32(sigmf(s1.y) * __uint_as_float(a1.y));
                u1.z = cvt_tf32(sigmf(s1.z) * __uint_as_float(a1.z));
                u1.w = cvt_tf32(sigmf(s1.w) * __uint_as_float(a1.w));
                *(uint4*)(g_ratf + rowB * NH + colb + c4 * 4) = u0;
                *(uint4*)(g_ratf + rowB * NH + colb + (c4 + 16) * 4) = u1;
            } else {
                *(float4*)(g_z + rowB * NH + n0A + c4 * 4) =
                    make_float4(sigmf(s0.x), sigmf(s0.y), sigmf(s0.z), sigmf(s0.w));
                *(float4*)(g_z + rowB * NH + n0A + (c4 + 16) * 4) =
                    make_float4(sigmf(s1.x), sigmf(s1.y), sigmf(s1.z), sigmf(s1.w));
            }
        }
        cnt_arrive(&g_rdone[ntA * 32]);

        // ---- Phase C: h~ partial = (r*a) @ Whh ----
        {
            cnt_wait(&g_rdone[(8 + ksC) * 32], tgt);

            FILL_WARP_STAGE(g_ratf, 0);
            FILL_WARP_STAGE(g_ratf, 1);

            float acc[2][4][4];
#pragma unroll
            for (int mt = 0; mt < 2; mt++)
#pragma unroll
                for (int nt = 0; nt < 4; nt++)
#pragma unroll
                    for (int c = 0; c < 4; c++) acc[mt][nt][c] = 0.f;

#pragma unroll
            for (int stg = 0; stg < 2; stg++) {
                if (stg == 0) CP_WAIT(1); else CP_WAIT(0);
                PAIR_BAR(pbar);
                const int* kks = stg == 0 ? kkset0 : kkset1;
#pragma unroll
                for (int q = 0; q < 8; q++) {
                    int kk = kks[q];
                    int k0 = kk * 8;
                    uint32_t a[2][4];
#pragma unroll
                    for (int mt = 0; mt < 2; mt++) {
                        const uint32_t* ap = As + (mbase + mt * 16 + gid) * STRA + k0 + tig;
                        a[mt][0] = ap[0];
                        a[mt][1] = ap[8 * STRA];
                        a[mt][2] = ap[4];
                        a[mt][3] = ap[8 * STRA + 4];
                    }
                    const ull* bp = BCf + (size_t)(kk * 8 + wn * 4) * 32 + lid;
#pragma unroll
                    for (int nt = 0; nt < 4; nt++) {
                        ull bb = bp[nt * 32];
                        uint32_t b0 = (uint32_t)bb, b1 = (uint32_t)(bb >> 32);
                        MMA_TF32(acc[0][nt], a[0], b0, b1);
                        MMA_TF32(acc[1][nt], a[1], b0, b1);
                    }
                }
            }
            float* dst = g_hpart[ksC];
#pragma unroll
            for (int mt = 0; mt < 2; mt++) {
                int m = mbase + mt * 16 + gid;
#pragma unroll
                for (int nt = 0; nt < 4; nt++) {
                    int n = n0C + wn * 32 + nt * 8 + tig * 2;
                    *(float2*)&dst[m * NH + n] =
                        make_float2(acc[mt][nt][0], acc[mt][nt][1]);
                    *(float2*)&dst[(m + 8) * NH + n] =
                        make_float2(acc[mt][nt][2], acc[mt][nt][3]);
                }
            }
        }
        gridbar(++gen);

        // ---- Phase D: h update; publish atf first, then stream out ----
        {
            float4 sh = phh;
#pragma unroll
            for (int ks = 0; ks < 8; ks++) {
                const float4* hp = (const float4*)(g_hpart[ks] + bid * NH);
                float4 v = hp[tid];
                sh.x += v.x; sh.y += v.y; sh.z += v.z; sh.w += v.w;
            }
            float4 zz = *(const float4*)(g_z + bid * NH + tid * 4);
            float4 aa = a_reg;
            float4 hn;
            hn.x = (1.f - zz.x) * aa.x + zz.x * tanhf(sh.x);
            hn.y = (1.f - zz.y) * aa.y + zz.y * tanhf(sh.y);
            hn.z = (1.f - zz.z) * aa.z + zz.z * tanhf(sh.z);
            hn.w = (1.f - zz.w) * aa.w + zz.w * tanhf(sh.w);
            if (t + 1 < NT) {
                float4 an = make_float4(gn.x * hn.x, gn.y * hn.y, gn.z * hn.z, gn.w * hn.w);
                a_reg = an;
                uint4 u;
                u.x = cvt_tf32(an.x); u.y = cvt_tf32(an.y);
                u.z = cvt_tf32(an.z); u.w = cvt_tf32(an.w);
                *(uint4*)(g_atf + bid * NH + tid * 4) = u;
            } else {
                *(float4*)(hlast + bid * NH + tid * 4) = hn;
            }
            STG_CS4(out + ((size_t)(bid * NT + t)) * NH + tid * 4, hn);
        }
        gridbar(++gen);
    }
}

// ---------------- launch -----------------------------------------------------
extern "C" void kernel_launch(void* const* d_in, const int* in_sizes, int n_in,
                              void* d_out, int out_size) {
    const float* value = (const float*)d_in[0];
    const float* delta = (const float*)d_in[1];
    const float* wdg   = (const float*)d_in[2];
    const float* wxz   = (const float*)d_in[3];
    const float* whz   = (const float*)d_in[4];
    const float* wxr   = (const float*)d_in[5];
    const float* whr   = (const float*)d_in[6];
    const float* wxh   = (const float*)d_in[7];
    const float* whh   = (const float*)d_in[8];
    const float* bdg   = (const float*)d_in[9];
    const float* bz    = (const float*)d_in[10];
    const float* br    = (const float*)d_in[11];
    const float* bh    = (const float*)d_in[12];
    float* out = (float*)d_out;
    float* hlast = out + ((size_t)out_size - (size_t)NB * NH);

    cudaFuncSetAttribute(k_persist, cudaFuncAttributeMaxDynamicSharedMemorySize, SMEM_DYN);

    k_xproj<<<dim3(24, 512), 256>>>(value, wxz, wxr, wxh, bz, br, bh);
    k_persist<<<NBLK, NTHR, SMEM_DYN>>>(delta, wdg, bdg, whz, whr, whh, out, hlast);
}

// round 17
// speedup vs baseline: 1.7865x; 1.0034x over previous
#include <cuda_runtime.h>
#include <math.h>
#include <stdint.h>

typedef unsigned long long ull;

#define NB 128
#define ND 256
#define NH 1024
#define NT 512
#define NH3 3072
#define NBLK 128
#define NTHR 256

// ---------------- scratch (static device globals) ---------------------------
__device__ float    g_P[(size_t)NT * NB * NH3];   // x-projections (+bias)
__device__ float    g_gamma[NT * NH];
__device__ uint32_t g_atf[NB * NH];               // a = gamma*h, tf32 bits
__device__ uint32_t g_ratf[NB * NH];              // r*a, tf32 bits
__device__ float    g_z[NB * NH];                 // z gates
__device__ float    g_zrpart[8][NB * 2 * NH];
__device__ float    g_hpart[8][NB * NH];

// ---------------- sync objects ------------------------------------------------
__device__ unsigned g_bar_count = 0;
__device__ volatile unsigned g_bar_gen = 0;
__device__ unsigned g_zrcnt[16 * 32];   // A done, per zr n-tile (8 arrivals/step)
__device__ unsigned g_rdone[16 * 32];   // B done, per zr n-tile (8)
__device__ unsigned g_hcnt[16 * 32];    // C done, per 64-col h tile (8)
__device__ unsigned g_ddone[16 * 32];   // D done, per 64-col tile (8)
__device__ unsigned g_afill[8 * 32];    // A fill done, per k-slice (16)

__device__ __forceinline__ void gridbar_atomic() {
    __syncthreads();
    if (threadIdx.x == 0) {
        unsigned gen = g_bar_gen;
        __threadfence();
        if (atomicAdd(&g_bar_count, 1) == NBLK - 1) {
            g_bar_count = 0;
            __threadfence();
            g_bar_gen = gen + 1;
        } else {
            while (g_bar_gen == gen) {}
            __threadfence();
        }
    }
    __syncthreads();
}

#define RED_ADD1(p) \
    asm volatile("red.global.add.u32 [%0], %1;" :: "l"(p), "r"(1u) : "memory")

__device__ __forceinline__ void cnt_arrive(unsigned* cnt) {
    __syncthreads();
    if (threadIdx.x == 0) { __threadfence(); RED_ADD1(cnt); }
}
__device__ __forceinline__ void spin(unsigned* cnt, unsigned target) {
    while (*(volatile unsigned*)cnt < target) {}
}

// ---------------- helpers ----------------------------------------------------
__device__ __forceinline__ float sigmf(float x) { return 1.f / (1.f + __expf(-x)); }

__device__ __forceinline__ uint32_t cvt_tf32(float x) {
    uint32_t r; asm("cvt.rna.tf32.f32 %0, %1;" : "=r"(r) : "f"(x)); return r;
}
__device__ __forceinline__ uint32_t smem_u32(const void* p) {
    uint32_t a;
    asm("{ .reg .u64 t; cvta.to.shared.u64 t, %1; cvt.u32.u64 %0, t; }" : "=r"(a) : "l"(p));
    return a;
}

#define MMA_TF32(d, a, b0, b1) \
    asm volatile("mma.sync.aligned.m16n8k8.row.col.f32.tf32.tf32.f32 " \
        "{%0,%1,%2,%3}, {%4,%5,%6,%7}, {%8,%9}, {%0,%1,%2,%3};" \
        : "+f"((d)[0]), "+f"((d)[1]), "+f"((d)[2]), "+f"((d)[3]) \
        : "r"((a)[0]), "r"((a)[1]), "r"((a)[2]), "r"((a)[3]), "r"(b0), "r"(b1))

#define CP_ASYNC16(dst_u32, src_ptr) \
    asm volatile("cp.async.cg.shared.global [%0], [%1], 16;" :: "r"(dst_u32), "l"(src_ptr) : "memory")
#define CP_COMMIT() asm volatile("cp.async.commit_group;" ::: "memory")
#define CP_WAIT(n)  asm volatile("cp.async.wait_group %0;" :: "n"(n) : "memory")

#define PAIR_BAR(id) asm volatile("bar.sync %0, 64;" :: "r"(id) : "memory")

#define STG_CS4(p, v) \
    asm volatile("st.global.cs.v4.f32 [%0], {%1,%2,%3,%4};" \
        :: "l"(p), "f"((v).x), "f"((v).y), "f"((v).z), "f"((v).w) : "memory")

// persist smem layout (bytes)
#define STRA      132
#define OFF_AS    0
#define OFF_BAF   67584
#define OFF_BCF   133120
#define SMEM_DYN  165888

#define FILL_WARP_STAGE(src, s) \
    do { \
        _Pragma("unroll") \
        for (int i = 0; i < 8; i++) { \
            int e = i * 32 + lid; \
            int row = e >> 3, kq = e & 7; \
            int m = mbase + row; \
            int k = wn * 64 + (s) * 32 + kq * 4; \
            uint32_t d = sb + OFF_AS + (uint32_t)(m * STRA + k) * 4; \
            CP_ASYNC16(d, (const void*)((src) + (size_t)m * NH + kbase + k)); \
        } \
        CP_COMMIT(); \
    } while (0)

// ---------------- x-projection GEMM (tf32 MMA, vectorized, 2 CTAs/SM) --------
__global__ __launch_bounds__(256, 2) void k_xproj(
    const float* __restrict__ value,
    const float* __restrict__ wxz, const float* __restrict__ wxr,
    const float* __restrict__ wxh,
    const float* __restrict__ bbz, const float* __restrict__ bbr,
    const float* __restrict__ bbh)
{
    __shared__ uint32_t As[32 * 132];
    __shared__ uint32_t Bs[128 * 36];
    const int n0 = blockIdx.x * 128;
    const int m0 = blockIdx.y * 128;
    const int gate = n0 >> 10;
    const int j0 = n0 & (NH - 1);
    const float* W    = (gate == 0) ? wxz : (gate == 1 ? wxr : wxh);
    const float* bias = (gate == 0) ? bbz : (gate == 1 ? bbr : bbh);
    const int b  = m0 >> 9;
    const int t0 = m0 & (NT - 1);
    const int tid = threadIdx.x;
    const int wid = tid >> 5, lid = tid & 31;
    const int gid = lid >> 2, tig = lid & 3;
    const int mbase = (wid & 3) * 32;
    const int nstrip = (wid >> 2) * 64;

    float acc[2][8][4];
#pragma unroll
    for (int mt = 0; mt < 2; mt++)
#pragma unroll
        for (int nt = 0; nt < 8; nt++)
#pragma unroll
            for (int c = 0; c < 4; c++) acc[mt][nt][c] = 0.f;

    const float* Abase = value + (size_t)b * ND * NT + t0;

    for (int kc = 0; kc < ND; kc += 32) {
#pragma unroll
        for (int it = 0; it < 4; it++) {
            int idx = it * 256 + tid;
            int m4 = idx & 31, k = idx >> 5;
            float4 v = __ldg((const float4*)(Abase + (size_t)(kc + k) * NT) + m4);
            uint4 w;
            w.x = cvt_tf32(v.x); w.y = cvt_tf32(v.y);
            w.z = cvt_tf32(v.z); w.w = cvt_tf32(v.w);
            *(uint4*)&As[k * 132 + m4 * 4] = w;
        }
#pragma unroll
        for (int it = 0; it < 4; it++) {
            int idx = it * 256 + tid;
            int n4 = idx & 31, k = idx >> 5;
            float4 v = __ldg((const float4*)(W + (size_t)(kc + k) * NH + j0) + n4);
            int n = n4 * 4;
            Bs[n * 36 + k]       = cvt_tf32(v.x);
            Bs[(n + 1) * 36 + k] = cvt_tf32(v.y);
            Bs[(n + 2) * 36 + k] = cvt_tf32(v.z);
            Bs[(n + 3) * 36 + k] = cvt_tf32(v.w);
        }
        __syncthreads();
#pragma unroll
        for (int kk = 0; kk < 4; kk++) {
            int k0 = kk * 8;
            uint32_t a[2][4];
#pragma unroll
            for (int mt = 0; mt < 2; mt++) {
                int m = mbase + mt * 16 + gid;
                a[mt][0] = As[(k0 + tig) * 132 + m];
                a[mt][1] = As[(k0 + tig) * 132 + m + 8];
                a[mt][2] = As[(k0 + tig + 4) * 132 + m];
                a[mt][3] = As[(k0 + tig + 4) * 132 + m + 8];
            }
#pragma unroll
            for (int nt = 0; nt < 8; nt++) {
                int n = nstrip + nt * 8 + gid;
                uint32_t b0 = Bs[n * 36 + k0 + tig];
                uint32_t b1 = Bs[n * 36 + k0 + tig + 4];
                MMA_TF32(acc[0][nt], a[0], b0, b1);
                MMA_TF32(acc[1][nt], a[1], b0, b1);
            }
        }
        __syncthreads();
    }
#pragma unroll
    for (int mt = 0; mt < 2; mt++) {
        int m = m0 + mbase + mt * 16 + gid;
#pragma unroll
        for (int nt = 0; nt < 8; nt++) {
            int nl = nstrip + nt * 8 + tig * 2;
            float b0v = bias[j0 + nl], b1v = bias[j0 + nl + 1];
            float* dst = g_P + (size_t)m * NH3 + n0 + nl;
            *(float2*)dst = make_float2(acc[mt][nt][0] + b0v, acc[mt][nt][1] + b1v);
            float* dst2 = g_P + (size_t)(m + 8) * NH3 + n0 + nl;
            *(float2*)dst2 = make_float2(acc[mt][nt][2] + b0v, acc[mt][nt][3] + b1v);
        }
    }
}

// ---------------- persistent recurrence (fully counter-synced) ---------------
__global__ __launch_bounds__(NTHR, 1) void k_persist(
    const float* __restrict__ delta,
    const float* __restrict__ wdg, const float* __restrict__ bdg,
    const float* __restrict__ whz, const float* __restrict__ whr,
    const float* __restrict__ whh,
    float* __restrict__ out, float* __restrict__ hlast)
{
    extern __shared__ char smem[];
    const uint32_t sb = smem_u32(smem);
    uint32_t* As  = (uint32_t*)(smem + OFF_AS);
    ull* BAf      = (ull*)(smem + OFF_BAF);
    ull* BCf      = (ull*)(smem + OFF_BCF);

    const int bid = blockIdx.x;
    const int tid = threadIdx.x;
    const int wid = tid >> 5;
    const int lid = tid & 31;
    const int gid = lid >> 2, tig = lid & 3;
    const int mbase = (wid & 3) * 32;
    const int wn    = wid >> 2;
    const int pbar  = 1 + (wid & 3);

    // unified block roles: nt = tile index, ks = k-slice / row-slice
    const int nt     = bid >> 3;            // 0..15
    const int ks     = bid & 7;             // 0..7
    const int n0A    = nt * 128;            // zr N base (tiles 0..15 over 2048)
    const int kbase  = ks * 128;
    const int gate   = n0A >> 10;
    const int j0     = n0A & (NH - 1);
    const int n0C    = nt * 64;             // h~ N base (tiles 0..15 over 1024)

    // B mapping: rows ks*16..+16, cols tile nt (128 wide, float4 chunks)
    const int rowB = ks * 16 + (tid >> 4);
    const int c4   = tid & 15;

    // D mapping: rows ks*16..+16, cols nt*64..+64
    const int rowD = rowB;
    const int colD = nt * 64 + (tid & 15) * 4;

    // ---- prologue: counter reset, gamma, zero state ----
    if (tid == 0) {
        if (bid < 16) {
            *(volatile unsigned*)&g_zrcnt[bid * 32] = 0;
            *(volatile unsigned*)&g_rdone[bid * 32] = 0;
            *(volatile unsigned*)&g_hcnt[bid * 32]  = 0;
            *(volatile unsigned*)&g_ddone[bid * 32] = 0;
        }
        if (bid < 8) *(volatile unsigned*)&g_afill[bid * 32] = 0;
    }

    for (int it = 0; it < 4; it++) {
        int idx4 = bid * 1024 + it * 256 + tid;
        int i = idx4 * 4;
        int t = i >> 10, j = i & (NH - 1);
        float d = delta[t];
        float4 w = *(const float4*)(wdg + j);
        float4 bb = *(const float4*)(bdg + j);
        float4 g;
        g.x = expf(-fmaxf(0.f, w.x * d + bb.x));
        g.y = expf(-fmaxf(0.f, w.y * d + bb.y));
        g.z = expf(-fmaxf(0.f, w.z * d + bb.z));
        g.w = expf(-fmaxf(0.f, w.w * d + bb.w));
        *(float4*)(g_gamma + i) = g;
    }
    float4 a_reg = make_float4(0.f, 0.f, 0.f, 0.f);   // a slice (rowD, colD..+4)
    *(uint4*)(g_atf + rowD * NH + colD) = make_uint4(0u, 0u, 0u, 0u);

    // ---- prologue: stationary weights -> fragment-order smem (tf32) ----
    {
        const float* Wzr = gate ? whr : whz;
#pragma unroll 1
        for (int it = 0; it < 64; it++) {
            int idx = it * 256 + tid;
            int n = idx & 127, k = idx >> 7;
            uint32_t bits = cvt_tf32(Wzr[(size_t)(kbase + k) * NH + j0 + n]);
            int kk = k >> 3, pos = k & 7, ntile = n >> 3, g = n & 7;
            int lane = g * 4 + (pos & 3), half = pos >> 2;
            *(uint32_t*)((char*)BAf + ((size_t)(kk * 16 + ntile) * 32 + lane) * 8 + half * 4) = bits;
        }
#pragma unroll 1
        for (int it = 0; it < 32; it++) {
            int idx = it * 256 + tid;
            int n = idx & 63, k = idx >> 6;
            uint32_t bits = cvt_tf32(whh[(size_t)(kbase + k) * NH + n0C + n]);
            int kk = k >> 3, pos = k & 7, ntile = n >> 3, g = n & 7;
            int lane = g * 4 + (pos & 3), half = pos >> 2;
            *(uint32_t*)((char*)BCf + ((size_t)(kk * 8 + ntile) * 32 + lane) * 8 + half * 4) = bits;
        }
    }
    gridbar_atomic();   // publishes resets + gamma + atf + weights

    const int kkset0[8] = {0, 1, 2, 3, 8, 9, 10, 11};
    const int kkset1[8] = {4, 5, 6, 7, 12, 13, 14, 15};

    for (int t = 0; t < NT; t++) {
        const unsigned t8  = 8u * (unsigned)(t + 1);
        const unsigned t8p = 8u * (unsigned)t;
        const unsigned t16 = 16u * (unsigned)(t + 1);

        // ---- prefetches ----
        const float4* PB = (const float4*)(g_P + ((size_t)(rowB * NT + t)) * NH3 + n0A);
        float4 pb0 = __ldg(PB + c4);
        float4 pb1 = __ldg(PB + c4 + 16);
        float4 phh = __ldg((const float4*)(g_P + ((size_t)(rowD * NT + t)) * NH3 + 2 * NH + colD));
        int tn = (t + 1 < NT) ? t + 1 : t;
        float4 gn = __ldg((const float4*)(g_gamma + tn * NH + colD));

        // ---- Phase A: zr partial = a @ [Whz|Whr] ----
        {
            if (tid == 0) {
                spin(&g_ddone[(2 * ks) * 32], t8p);       // atf cols ready
                spin(&g_ddone[(2 * ks + 1) * 32], t8p);
                spin(&g_rdone[nt * 32], t8p);             // zrpart WAR
                __threadfence();
            }
            __syncthreads();

            FILL_WARP_STAGE(g_atf, 0);
            FILL_WARP_STAGE(g_atf, 1);

            float acc[2][8][4];
#pragma unroll
            for (int mt = 0; mt < 2; mt++)
#pragma unroll
                for (int ntt = 0; ntt < 8; ntt++)
#pragma unroll
                    for (int c = 0; c < 4; c++) acc[mt][ntt][c] = 0.f;

#pragma unroll
            for (int stg = 0; stg < 2; stg++) {
                if (stg == 0) CP_WAIT(1); else CP_WAIT(0);
                PAIR_BAR(pbar);
                const int* kks = stg == 0 ? kkset0 : kkset1;
#pragma unroll
                for (int q = 0; q < 8; q++) {
                    int kk = kks[q];
                    int k0 = kk * 8;
                    uint32_t a[2][4];
#pragma unroll
                    for (int mt = 0; mt < 2; mt++) {
                        const uint32_t* ap = As + (mbase + mt * 16 + gid) * STRA + k0 + tig;
                        a[mt][0] = ap[0];
                        a[mt][1] = ap[8 * STRA];
                        a[mt][2] = ap[4];
                        a[mt][3] = ap[8 * STRA + 4];
                    }
                    const ull* bp = BAf + (size_t)(kk * 16 + wn * 8) * 32 + lid;
#pragma unroll
                    for (int ntt = 0; ntt < 8; ntt++) {
                        ull bb = bp[ntt * 32];
                        uint32_t b0 = (uint32_t)bb, b1 = (uint32_t)(bb >> 32);
                        MMA_TF32(acc[0][ntt], a[0], b0, b1);
                        MMA_TF32(acc[1][ntt], a[1], b0, b1);
                    }
                }
            }
            cnt_arrive(&g_afill[ks * 32]);       // atf reads complete

            float* dst = g_zrpart[ks];
#pragma unroll
            for (int mt = 0; mt < 2; mt++) {
                int m = mbase + mt * 16 + gid;
#pragma unroll
                for (int ntt = 0; ntt < 8; ntt++) {
                    int n = n0A + wn * 64 + ntt * 8 + tig * 2;
                    *(float2*)&dst[m * (2 * NH) + n] =
                        make_float2(acc[mt][ntt][0], acc[mt][ntt][1]);
                    *(float2*)&dst[(m + 8) * (2 * NH) + n] =
                        make_float2(acc[mt][ntt][2], acc[mt][ntt][3]);
                }
            }
        }
        cnt_arrive(&g_zrcnt[nt * 32]);

        // ---- Phase B: gates for tile nt, rows [ks*16, +16) ----
        {
            if (tid == 0) {
                spin(&g_zrcnt[nt * 32], t8);
                if (nt >= 8) {                    // reads atf(t)
                    spin(&g_ddone[(2 * (nt - 8)) * 32], t8p);
                    spin(&g_ddone[(2 * (nt - 8) + 1) * 32], t8p);
                }
                __threadfence();
            }
            __syncthreads();

            float4 s0 = pb0, s1 = pb1;
#pragma unroll
            for (int kss = 0; kss < 8; kss++) {
                const float4* zp = (const float4*)(g_zrpart[kss] + rowB * 2 * NH + n0A);
                float4 v0 = zp[c4];
                s0.x += v0.x; s0.y += v0.y; s0.z += v0.z; s0.w += v0.w;
                float4 v1 = zp[c4 + 16];
                s1.x += v1.x; s1.y += v1.y; s1.z += v1.z; s1.w += v1.w;
            }
            if (nt >= 8) {
                int colb = (nt - 8) * 128;
                uint4 a0 = *(const uint4*)(g_atf + rowB * NH + colb + c4 * 4);
                uint4 a1 = *(const uint4*)(g_atf + rowB * NH + colb + (c4 + 16) * 4);
                uint4 u0, u1;
                u0.x = cvt_tf32(sigmf(s0.x) * __uint_as_float(a0.x));
                u0.y = cvt_tf32(sigmf(s0.y) * __uint_as_float(a0.y));
                u0.z = cvt_tf32(sigmf(s0.z) * __uint_as_float(a0.z));
                u0.w = cvt_tf32(sigmf(s0.w) * __uint_as_float(a0.w));
                u1.x = cvt_tf32(sigmf(s1.x) * __uint_as_float(a1.x));
                u1.y = cvt_tf32(sigmf(s1.y) * __uint_as_float(a1.y));
                u1.z = cvt_tf32(sigmf(s1.z) * __uint_as_float(a1.z));
                u1.w = cvt_tf32(sigmf(s1.w) * __uint_as_float(a1.w));
                *(uint4*)(g_ratf + rowB * NH + colb + c4 * 4) = u0;
                *(uint4*)(g_ratf + rowB * NH + colb + (c4 + 16) * 4) = u1;
            } else {
                *(float4*)(g_z + rowB * NH + n0A + c4 * 4) =
                    make_float4(sigmf(s0.x), sigmf(s0.y), sigmf(s0.z), sigmf(s0.w));
                *(float4*)(g_z + rowB * NH + n0A + (c4 + 16) * 4) =
                    make_float4(sigmf(s1.x), sigmf(s1.y), sigmf(s1.z), sigmf(s1.w));
            }
        }
        cnt_arrive(&g_rdone[nt * 32]);

        // ---- Phase C: h~ partial = (r*a) @ Whh ----
        {
            if (tid == 0) {
                spin(&g_rdone[(8 + ks) * 32], t8);    // ratf k-slice ready
                __threadfence();
            }
            __syncthreads();

            FILL_WARP_STAGE(g_ratf, 0);
            FILL_WARP_STAGE(g_ratf, 1);

            float acc[2][4][4];
#pragma unroll
            for (int mt = 0; mt < 2; mt++)
#pragma unroll
                for (int ntt = 0; ntt < 4; ntt++)
#pragma unroll
                    for (int c = 0; c < 4; c++) acc[mt][ntt][c] = 0.f;

#pragma unroll
            for (int stg = 0; stg < 2; stg++) {
                if (stg == 0) CP_WAIT(1); else CP_WAIT(0);
                PAIR_BAR(pbar);
                const int* kks = stg == 0 ? kkset0 : kkset1;
#pragma unroll
                for (int q = 0; q < 8; q++) {
                    int kk = kks[q];
                    int k0 = kk * 8;
                    uint32_t a[2][4];
#pragma unroll
                    for (int mt = 0; mt < 2; mt++) {
                        const uint32_t* ap = As + (mbase + mt * 16 + gid) * STRA + k0 + tig;
                        a[mt][0] = ap[0];
                        a[mt][1] = ap[8 * STRA];
                        a[mt][2] = ap[4];
                        a[mt][3] = ap[8 * STRA + 4];
                    }
                    const ull* bp = BCf + (size_t)(kk * 8 + wn * 4) * 32 + lid;
#pragma unroll
                    for (int ntt = 0; ntt < 4; ntt++) {
                        ull bb = bp[ntt * 32];
                        uint32_t b0 = (uint32_t)bb, b1 = (uint32_t)(bb >> 32);
                        MMA_TF32(acc[0][ntt], a[0], b0, b1);
                        MMA_TF32(acc[1][ntt], a[1], b0, b1);
                    }
                }
            }
            float* dst = g_hpart[ks];
#pragma unroll
            for (int mt = 0; mt < 2; mt++) {
                int m = mbase + mt * 16 + gid;
#pragma unroll
                for (int ntt = 0; ntt < 4; ntt++) {
                    int n = n0C + wn * 32 + ntt * 8 + tig * 2;
                    *(float2*)&dst[m * NH + n] =
                        make_float2(acc[mt][ntt][0], acc[mt][ntt][1]);
                    *(float2*)&dst[(m + 8) * NH + n] =
                        make_float2(acc[mt][ntt][2], acc[mt][ntt][3]);
                }
            }
        }
        cnt_arrive(&g_hcnt[nt * 32]);

        // ---- Phase D: h update for rows [ks*16,+16) x cols [nt*64,+64) ----
        {
            if (tid == 0) {
                spin(&g_hcnt[nt * 32], t8);               // hpart tile ready
                spin(&g_rdone[(nt >> 1) * 32], t8);       // z ready
                spin(&g_rdone[(8 + (nt >> 1)) * 32], t8); // atf WAR: B readers done
                spin(&g_afill[(nt >> 1) * 32], t16);      // atf WAR: A readers done
                __threadfence();
            }
            __syncthreads();

            float4 sh = phh;
#pragma unroll
            for (int kss = 0; kss < 8; kss++) {
                float4 v = *(const float4*)(g_hpart[kss] + rowD * NH + colD);
                sh.x += v.x; sh.y += v.y; sh.z += v.z; sh.w += v.w;
            }
            float4 zz = *(const float4*)(g_z + rowD * NH + colD);
            float4 aa = a_reg;
            float4 hn;
            hn.x = (1.f - zz.x) * aa.x + zz.x * tanhf(sh.x);
            hn.y = (1.f - zz.y) * aa.y + zz.y * tanhf(sh.y);
            hn.z = (1.f - zz.z) * aa.z + zz.z * tanhf(sh.z);
            hn.w = (1.f - zz.w) * aa.w + zz.w * tanhf(sh.w);
            if (t + 1 < NT) {
                float4 an = make_float4(gn.x * hn.x, gn.y * hn.y, gn.z * hn.z, gn.w * hn.w);
                a_reg = an;
                uint4 u;
                u.x = cvt_tf32(an.x); u.y = cvt_tf32(an.y);
                u.z = cvt_tf32(an.z); u.w = cvt_tf32(an.w);
                *(uint4*)(g_atf + rowD * NH + colD) = u;
            } else {
                *(float4*)(hlast + rowD * NH + colD) = hn;
            }
            STG_CS4(out + ((size_t)(rowD * NT + t)) * NH + colD, hn);
        }
        cnt_arrive(&g_ddone[nt * 32]);
    }
}

// ---------------- launch -----------------------------------------------------
extern "C" void kernel_launch(void* const* d_in, const int* in_sizes, int n_in,
                              void* d_out, int out_size) {
    const float* value = (const float*)d_in[0];
    const float* delta = (const float*)d_in[1];
    const float* wdg   = (const float*)d_in[2];
    const float* wxz   = (const float*)d_in[3];
    const float* whz   = (const float*)d_in[4];
    const float* wxr   = (const float*)d_in[5];
    const float* whr   = (const float*)d_in[6];
    const float* wxh   = (const float*)d_in[7];
    const float* whh   = (const float*)d_in[8];
    const float* bdg   = (const float*)d_in[9];
    const float* bz    = (const float*)d_in[10];
    const float* br    = (const float*)d_in[11];
    const float* bh    = (const float*)d_in[12];
    float* out = (float*)d_out;
    float* hlast = out + ((size_t)out_size - (size_t)NB * NH);

    cudaFuncSetAttribute(k_persist, cudaFuncAttributeMaxDynamicSharedMemorySize, SMEM_DYN);

    k_xproj<<<dim3(24, 512), 256>>>(value, wxz, wxr, wxh, bz, br, bh);
    k_persist<<<NBLK, NTHR, SMEM_DYN>>>(delta, wdg, bdg, whz, whr, whh, out, hlast);
}